// round 5
// baseline (speedup 1.0000x reference)
#include <cuda_runtime.h>
#include <cuda_bf16.h>

#define NATOMS 256
#define PDIM 2
#define LDIM 9
#define FDIM 64
#define ROWLEN (PDIM*LDIM*FDIM)                 // 1152 floats per (a,b)
#define GK (NATOMS*ROWLEN)                      // 294912 = K of the big GEMM
#define NROWS_TOTAL (NATOMS*NATOMS*PDIM*LDIM)   // 1,179,648 rows of 64

// ---------------- scratch (static device globals; no runtime alloc) ----------
__device__ __nv_bfloat16  g_Thi[NATOMS * GK];     // bf16 hi(T)
__device__ __nv_bfloat16  g_Tlo[NATOMS * GK];     // bf16 lo(T)
__device__ __nv_bfloat16  g_xhi[NATOMS * GK];     // bf16 hi(x)
__device__ __nv_bfloat16  g_xlo[NATOMS * GK];     // bf16 lo(x)
__device__ float g_M[PDIM * FDIM * FDIM];         // M_p = Wq_p Wk_p^T
__device__ float g_dotb[NATOMS * NATOMS];         // split-GEMM logits (accurate)
__device__ float g_w[NATOMS * NATOMS];
__device__ int   g_idx[NATOMS * NATOMS];
__device__ float g_wval[NATOMS * NATOMS];
__device__ int   g_nnz[NATOMS];
__device__ int   g_ccol[NATOMS];                  // columns needing exact recompute
__device__ int   g_calist[NATOMS * 8];            // a-lists per such column
__device__ int   g_cak[NATOMS];
__device__ int   g_nccols;

// ---------------- packed f32x2 helpers (sm_103a FFMA2) -----------------------
static __device__ __forceinline__ unsigned long long pk2(float lo, float hi) {
    unsigned long long r;
    asm("mov.b64 %0, {%1, %2};" : "=l"(r) : "f"(lo), "f"(hi));
    return r;
}
static __device__ __forceinline__ void upk2(float& lo, float& hi, unsigned long long v) {
    asm("mov.b64 {%0, %1}, %2;" : "=f"(lo), "=f"(hi) : "l"(v));
}
static __device__ __forceinline__ void fma2(unsigned long long& d,
                                            unsigned long long a, unsigned long long b) {
    asm("fma.rn.f32x2 %0, %1, %2, %0;" : "+l"(d) : "l"(a), "l"(b));
}

// ---------------- K0: init accumulators (re-run every replay) ---------------
__global__ void k0_zero() {
    int i = blockIdx.x * blockDim.x + threadIdx.x;
    if (i < NATOMS * NATOMS) g_dotb[i] = 0.0f;
    if (i < NATOMS) g_nnz[i] = 0;
    if (i == 0) g_nccols = 0;
}

// ---------------- K1: M[p][e][f] = sum_g Wq[p][e][g] * Wk[p][f][g] ----------
__global__ void k1_M(const float* __restrict__ Wq, const float* __restrict__ Wk) {
    int id = blockIdx.x * blockDim.x + threadIdx.x;
    if (id >= PDIM * FDIM * FDIM) return;
    int p = id >> 12;
    int e = (id >> 6) & 63;
    int f = id & 63;
    const float* q = Wq + (p << 12) + (e << 6);
    const float* k = Wk + (p << 12) + (f << 6);
    float s = 0.0f;
#pragma unroll 16
    for (int g = 0; g < 64; g++) s += q[g] * k[g];
    g_M[id] = s;
}

static __device__ __forceinline__ unsigned pack_hi2(float a, float b) {
    __nv_bfloat162 h2 = __floats2bfloat162_rn(a, b);
    return *reinterpret_cast<unsigned*>(&h2);
}
static __device__ __forceinline__ unsigned pack_lo2(float a, float b) {
    float ra = a - __bfloat162float(__float2bfloat16_rn(a));
    float rb = b - __bfloat162float(__float2bfloat16_rn(b));
    __nv_bfloat162 h2 = __floats2bfloat162_rn(ra, rb);
    return *reinterpret_cast<unsigned*>(&h2);
}

// ---------------- K2: T = x*M (fp32 via FFMA2), emit hi/lo bf16 of T and x ---
__global__ __launch_bounds__(256, 2) void k2_T(const float* __restrict__ x) {
    __shared__ float xS[256 * 65];
    __shared__ float MS[PDIM * FDIM * FDIM];
    int t = threadIdx.x;
    int r0 = blockIdx.x * 256;
    const float* gx = x + (size_t)r0 * 64;

#pragma unroll
    for (int i = 0; i < 16; i++) {
        float4 v = *(const float4*)(gx + i * 1024 + t * 4);
        int row = i * 16 + (t >> 4);
        int e   = (t & 15) * 4;
        float* d = xS + row * 65 + e;
        d[0] = v.x; d[1] = v.y; d[2] = v.z; d[3] = v.w;
    }
#pragma unroll
    for (int i = 0; i < 8; i++)
        *(float4*)(MS + i * 1024 + t * 4) = *(const float4*)(g_M + i * 1024 + t * 4);
    __syncthreads();

    int r = r0 + t;
    int p = (r / LDIM) & 1;
    const ulonglong2* Mp2 = (const ulonglong2*)(MS + (p << 12));
    const float* xrow = xS + t * 65;

    unsigned long long acc2[32];
#pragma unroll
    for (int j = 0; j < 32; j++) acc2[j] = 0ULL;

#pragma unroll 4
    for (int e = 0; e < 64; e++) {
        float xv = xrow[e];
        unsigned long long xx = pk2(xv, xv);
#pragma unroll
        for (int q = 0; q < 16; q++) {
            ulonglong2 m = Mp2[e * 16 + q];
            fma2(acc2[2 * q],     xx, m.x);
            fma2(acc2[2 * q + 1], xx, m.y);
        }
    }

    float acc[64];
#pragma unroll
    for (int j = 0; j < 32; j++) upk2(acc[2 * j], acc[2 * j + 1], acc2[j]);

    uint4* thh = (uint4*)(g_Thi + (size_t)r * 64);
    uint4* thl = (uint4*)(g_Tlo + (size_t)r * 64);
    uint4* xhh = (uint4*)(g_xhi + (size_t)r * 64);
    uint4* xhl = (uint4*)(g_xlo + (size_t)r * 64);
#pragma unroll
    for (int i = 0; i < 8; i++) {
        const float* a = acc + i * 8;
        const float* xr = xrow + i * 8;
        uint4 vh, vl, wh, wl;
        vh.x = pack_hi2(a[0], a[1]); vh.y = pack_hi2(a[2], a[3]);
        vh.z = pack_hi2(a[4], a[5]); vh.w = pack_hi2(a[6], a[7]);
        vl.x = pack_lo2(a[0], a[1]); vl.y = pack_lo2(a[2], a[3]);
        vl.z = pack_lo2(a[4], a[5]); vl.w = pack_lo2(a[6], a[7]);
        wh.x = pack_hi2(xr[0], xr[1]); wh.y = pack_hi2(xr[2], xr[3]);
        wh.z = pack_hi2(xr[4], xr[5]); wh.w = pack_hi2(xr[6], xr[7]);
        wl.x = pack_lo2(xr[0], xr[1]); wl.y = pack_lo2(xr[2], xr[3]);
        wl.z = pack_lo2(xr[4], xr[5]); wl.w = pack_lo2(xr[6], xr[7]);
        thh[i] = vh; thl[i] = vl; xhh[i] = wh; xhl[i] = wl;
    }
}

// ---------------- K3s: dotb = Thi*xhi^T + Thi*xlo^T + Tlo*xhi^T (mma bf16) ---
#define K3_KCHUNK 4096
#define PITCH 16
#define STAGE_BYTES (128 * PITCH * 2)   // 4096

static __device__ __forceinline__ void cpa16(unsigned sdst, const void* gsrc) {
    asm volatile("cp.async.cg.shared.global [%0], [%1], 16;\n" :: "r"(sdst), "l"(gsrc));
}
static __device__ __forceinline__ void ldsm_x4(unsigned r[4], unsigned addr) {
    asm volatile("ldmatrix.sync.aligned.m8n8.x4.shared.b16 {%0,%1,%2,%3}, [%4];\n"
        : "=r"(r[0]), "=r"(r[1]), "=r"(r[2]), "=r"(r[3]) : "r"(addr));
}
static __device__ __forceinline__ void mma_bf16(float d[4], const unsigned a[4],
                                                const unsigned b0, const unsigned b1) {
    asm volatile("mma.sync.aligned.m16n8k16.row.col.f32.bf16.bf16.f32 "
        "{%0,%1,%2,%3},{%4,%5,%6,%7},{%8,%9},{%0,%1,%2,%3};\n"
        : "+f"(d[0]), "+f"(d[1]), "+f"(d[2]), "+f"(d[3])
        : "r"(a[0]), "r"(a[1]), "r"(a[2]), "r"(a[3]), "r"(b0), "r"(b1));
}

__global__ __launch_bounds__(256, 2) void k3s_dot() {
    __shared__ __nv_bfloat16 Ah[3][128 * PITCH];
    __shared__ __nv_bfloat16 Al[3][128 * PITCH];
    __shared__ __nv_bfloat16 Bh[3][128 * PITCH];
    __shared__ __nv_bfloat16 Bl[3][128 * PITCH];
    const int t = threadIdx.x;
    const int m0 = blockIdx.x * 128, n0 = blockIdx.y * 128;
    const size_t kb = (size_t)blockIdx.z * K3_KCHUNK;

    const unsigned uAh = (unsigned)__cvta_generic_to_shared(&Ah[0][0]);
    const unsigned uAl = (unsigned)__cvta_generic_to_shared(&Al[0][0]);
    const unsigned uBh = (unsigned)__cvta_generic_to_shared(&Bh[0][0]);
    const unsigned uBl = (unsigned)__cvta_generic_to_shared(&Bl[0][0]);

    const int row = t >> 1, half = t & 1;
    const size_t goff = (size_t)row * GK + kb + half * 8;
    const __nv_bfloat16* gah = g_Thi + (size_t)m0 * GK + goff;
    const __nv_bfloat16* gal = g_Tlo + (size_t)m0 * GK + goff;
    const __nv_bfloat16* gbh = g_xhi + (size_t)n0 * GK + goff;
    const __nv_bfloat16* gbl = g_xlo + (size_t)n0 * GK + goff;
    const unsigned soff = (row * PITCH + half * 8) * 2;

    const int NS = K3_KCHUNK / 16;   // 256 k-steps

#pragma unroll
    for (int s = 0; s < 2; s++) {
        cpa16(uAh + soff + s * STAGE_BYTES, gah + (size_t)s * 16);
        cpa16(uAl + soff + s * STAGE_BYTES, gal + (size_t)s * 16);
        cpa16(uBh + soff + s * STAGE_BYTES, gbh + (size_t)s * 16);
        cpa16(uBl + soff + s * STAGE_BYTES, gbl + (size_t)s * 16);
        asm volatile("cp.async.commit_group;\n");
    }

    const int warp = t >> 5, lane = t & 31;
    const int wm = warp >> 2, wn = warp & 3;
    const unsigned aoff = ((wm * 64 + (lane & 15)) * PITCH + (lane >> 4) * 8) * 2;
    const unsigned boff = ((wn * 32 + (lane & 15)) * PITCH + (lane >> 4) * 8) * 2;

    float acc[4][4][4] = {};

    int buf = 0, pbuf = 2;
    for (int ks = 0; ks < NS; ks++) {
        asm volatile("cp.async.wait_group %0;\n" :: "n"(1));
        __syncthreads();

        unsigned bh[2][4], bl[2][4];
#pragma unroll
        for (int j = 0; j < 2; j++) {
            ldsm_x4(bh[j], uBh + boff + buf * STAGE_BYTES + j * 16 * PITCH * 2);
            ldsm_x4(bl[j], uBl + boff + buf * STAGE_BYTES + j * 16 * PITCH * 2);
        }
#pragma unroll
        for (int i = 0; i < 4; i++) {
            unsigned ah[4], al[4];
            ldsm_x4(ah, uAh + aoff + buf * STAGE_BYTES + i * 16 * PITCH * 2);
            ldsm_x4(al, uAl + aoff + buf * STAGE_BYTES + i * 16 * PITCH * 2);
#pragma unroll
            for (int j = 0; j < 4; j++) {
                unsigned bh0 = bh[j >> 1][(j & 1)], bh1 = bh[j >> 1][(j & 1) + 2];
                unsigned bl0 = bl[j >> 1][(j & 1)], bl1 = bl[j >> 1][(j & 1) + 2];
                mma_bf16(acc[i][j], ah, bh0, bh1);
                mma_bf16(acc[i][j], ah, bl0, bl1);
                mma_bf16(acc[i][j], al, bh0, bh1);
            }
        }

        const int pf = ks + 2;
        if (pf < NS) {
            cpa16(uAh + soff + pbuf * STAGE_BYTES, gah + (size_t)pf * 16);
            cpa16(uAl + soff + pbuf * STAGE_BYTES, gal + (size_t)pf * 16);
            cpa16(uBh + soff + pbuf * STAGE_BYTES, gbh + (size_t)pf * 16);
            cpa16(uBl + soff + pbuf * STAGE_BYTES, gbl + (size_t)pf * 16);
        }
        asm volatile("cp.async.commit_group;\n");
        buf = (buf == 2) ? 0 : buf + 1;
        pbuf = (pbuf == 2) ? 0 : pbuf + 1;
    }
    asm volatile("cp.async.wait_group 0;\n");

    const int lr = lane >> 2, lc = (lane & 3) * 2;
#pragma unroll
    for (int i = 0; i < 4; i++)
#pragma unroll
        for (int j = 0; j < 4; j++) {
            int r = m0 + wm * 64 + i * 16 + lr;
            int c = n0 + wn * 32 + j * 8 + lc;
            atomicAdd(&g_dotb[r * NATOMS + c],           acc[i][j][0]);
            atomicAdd(&g_dotb[r * NATOMS + c + 1],       acc[i][j][1]);
            atomicAdd(&g_dotb[(r + 8) * NATOMS + c],     acc[i][j][2]);
            atomicAdd(&g_dotb[(r + 8) * NATOMS + c + 1], acc[i][j][3]);
        }
}

// ---------------- K4b: find columns with >=2 entries within gap 14 -----------
#define CLOSE_MARGIN 14.0f
__global__ void k4b_close() {
    int c = blockIdx.x, t = threadIdx.x;
    __shared__ float red[256];
    __shared__ int cnt, pos;
    if (t == 0) { cnt = 0; pos = 0; }
    float v = g_dotb[t * NATOMS + c];
    red[t] = v; __syncthreads();
    for (int s = 128; s > 0; s >>= 1) {
        if (t < s) red[t] = fmaxf(red[t], red[t + s]);
        __syncthreads();
    }
    float mx = red[0];
    bool cand = (v >= mx - CLOSE_MARGIN);
    if (cand) atomicAdd(&cnt, 1);
    __syncthreads();
    if (cnt >= 2) {
        if (t == 0) { int s = atomicAdd(&g_nccols, 1); g_ccol[s] = c; }
        if (cand) {
            int p = atomicAdd(&pos, 1);
            if (p < 8) { g_calist[c * 8 + p] = t; g_dotb[t * NATOMS + c] = 0.0f; }
        }
        __syncthreads();
        if (t == 0) g_cak[c] = (cnt < 8) ? cnt : 8;
    }
}

// ---------------- K5x: exact fp32 logits for close columns, from x & M -------
__global__ __launch_bounds__(256) void k5x_exact(const float* __restrict__ x) {
    __shared__ float Msh[2 * 4096];
    __shared__ float red[256];
    int s = blockIdx.y;
    if (s >= g_nccols) return;
    int t = threadIdx.x;
    int c = g_ccol[s];
    int ka = g_cak[c];

    for (int i = t; i < 8192 / 4; i += 256)
        ((float4*)Msh)[i] = ((const float4*)g_M)[i];
    __syncthreads();

    int row = blockIdx.x * 256 + t;        // [0, 4608)
    int p = (row / LDIM) & 1;
    const float* Mp = Msh + (p << 12);

    float xc[64];
    {
        const float4* xcp = (const float4*)(x + (size_t)c * GK + (size_t)row * 64);
#pragma unroll
        for (int i = 0; i < 16; i++) {
            float4 v = xcp[i];
            xc[4*i] = v.x; xc[4*i+1] = v.y; xc[4*i+2] = v.z; xc[4*i+3] = v.w;
        }
    }
    float z[64];
#pragma unroll 4
    for (int e = 0; e < 64; e++) {
        const float4* Mr = (const float4*)(Mp + e * 64);
        float sm = 0.0f;
#pragma unroll
        for (int f4 = 0; f4 < 16; f4++) {
            float4 m = Mr[f4];
            sm += m.x * xc[4*f4] + m.y * xc[4*f4+1] + m.z * xc[4*f4+2] + m.w * xc[4*f4+3];
        }
        z[e] = sm;
    }

    for (int j = 0; j < ka; j++) {
        int a = g_calist[c * 8 + j];
        const float4* xap = (const float4*)(x + (size_t)a * GK + (size_t)row * 64);
        float sd = 0.0f;
#pragma unroll
        for (int i = 0; i < 16; i++) {
            float4 v = xap[i];
            sd += v.x * z[4*i] + v.y * z[4*i+1] + v.z * z[4*i+2] + v.w * z[4*i+3];
        }
        red[t] = sd; __syncthreads();
        for (int st = 128; st > 0; st >>= 1) {
            if (t < st) red[t] += red[t + st];
            __syncthreads();
        }
        if (t == 0) atomicAdd(&g_dotb[a * NATOMS + c], red[0]);
        __syncthreads();
    }
}

// ---------------- K4: softmax over axis a (per column c) ---------------------
__global__ void k4_softmax() {
    int c = blockIdx.x, t = threadIdx.x;
    __shared__ float red[256];
    float v = g_dotb[t * NATOMS + c];
    red[t] = v; __syncthreads();
    for (int s = 128; s > 0; s >>= 1) {
        if (t < s) red[t] = fmaxf(red[t], red[t + s]);
        __syncthreads();
    }
    float mx = red[0]; __syncthreads();
    float e = expf(v - mx);
    red[t] = e; __syncthreads();
    for (int s = 128; s > 0; s >>= 1) {
        if (t < s) red[t] += red[t + s];
        __syncthreads();
    }
    g_w[t * NATOMS + c] = e / red[0];
}

// ---------------- K5: compact significant weights per output row a -----------
__global__ void k5_compact() {
    int a = blockIdx.x, t = threadIdx.x;
    float wv = g_w[a * NATOMS + t];
    bool nz = (wv > 1e-7f);
    unsigned m = __ballot_sync(0xffffffffu, nz);
    int lane = t & 31, warp = t >> 5;
    int pre = __popc(m & ((1u << lane) - 1u));
    __shared__ int wcnt[8], woff[8];
    if (lane == 0) wcnt[warp] = __popc(m);
    __syncthreads();
    if (t == 0) {
        int s = 0;
        for (int i = 0; i < 8; i++) { woff[i] = s; s += wcnt[i]; }
        g_nnz[a] = s;
    }
    __syncthreads();
    if (nz) {
        int pos = woff[warp] + pre;
        g_idx[a * NATOMS + pos]  = t;
        g_wval[a * NATOMS + pos] = wv;
    }
}

// ---------------- K6: out[a,row,f] = (sum_j w_j x[b_j,row,:]) * Wv[p] --------
__global__ __launch_bounds__(256, 2) void k6_out(const float* __restrict__ x,
                                                 const float* __restrict__ Wv,
                                                 float* __restrict__ out) {
    __shared__ float yS[256 * 65];
    __shared__ float WS[PDIM * FDIM * FDIM];
    __shared__ float wlist[NATOMS];
    __shared__ int   blist[NATOMS];
    __shared__ int   s_nnz;
    int t = threadIdx.x;
    int a = blockIdx.y;
    int r0 = blockIdx.x * 256;

    if (t == 0) s_nnz = g_nnz[a];
    __syncthreads();
    int nnz = s_nnz;

    if (nnz == 0) {   // entire output slab is zero
        float4* dst = (float4*)(out + (size_t)a * GK + (size_t)(r0 + t) * 64);
        float4 z = make_float4(0.f, 0.f, 0.f, 0.f);
#pragma unroll
        for (int i = 0; i < 16; i++) dst[i] = z;
        return;
    }

#pragma unroll
    for (int i = 0; i < 8; i++)
        *(float4*)(WS + i * 1024 + t * 4) = *(const float4*)(Wv + i * 1024 + t * 4);
    if (t < nnz) { blist[t] = g_idx[a * NATOMS + t]; wlist[t] = g_wval[a * NATOMS + t]; }
    __syncthreads();

    // phase 1: y[row][e] = sum_j w_j * x[b_j, r0+row, e]   (packed f32x2)
    int rowt = t >> 4;
    int e4   = (t & 15) * 4;
#pragma unroll 2
    for (int i = 0; i < 16; i++) {
        int row = i * 16 + rowt;
        size_t off = (size_t)(r0 + row) * 64 + e4;
        unsigned long long a01 = 0ULL, a23 = 0ULL;
        for (int j = 0; j < nnz; j++) {
            const ulonglong2 v = *(const ulonglong2*)(x + (size_t)blist[j] * GK + off);
            float w = wlist[j];
            unsigned long long ww = pk2(w, w);
            fma2(a01, ww, v.x);
            fma2(a23, ww, v.y);
        }
        float* d = yS + row * 65 + e4;
        upk2(d[0], d[1], a01);
        upk2(d[2], d[3], a23);
    }
    __syncthreads();

    // phase 2: out[row][f] = sum_e y[row][e]*Wv[p][e][f]  (packed f32x2)
    int rg = r0 + t;
    int p = (rg / LDIM) & 1;
    const ulonglong2* Wp2 = (const ulonglong2*)(WS + (p << 12));
    const float* yrow = yS + t * 65;

    unsigned long long acc2[32];
#pragma unroll
    for (int j = 0; j < 32; j++) acc2[j] = 0ULL;

#pragma unroll 4
    for (int e = 0; e < 64; e++) {
        float yv = yrow[e];
        unsigned long long yy = pk2(yv, yv);
#pragma unroll
        for (int q = 0; q < 16; q++) {
            ulonglong2 m = Wp2[e * 16 + q];
            fma2(acc2[2 * q],     yy, m.x);
            fma2(acc2[2 * q + 1], yy, m.y);
        }
    }

    float4* dst = (float4*)(out + (size_t)a * GK + (size_t)rg * 64);
#pragma unroll
    for (int i = 0; i < 16; i++) {
        float4 o;
        upk2(o.x, o.y, acc2[2 * i]);
        upk2(o.z, o.w, acc2[2 * i + 1]);
        dst[i] = o;
    }
}

// ---------------- launch ------------------------------------------------------
extern "C" void kernel_launch(void* const* d_in, const int* in_sizes, int n_in,
                              void* d_out, int out_size) {
    const float* x  = (const float*)d_in[0];
    const float* Wq = (const float*)d_in[1];
    const float* Wk = (const float*)d_in[2];
    const float* Wv = (const float*)d_in[3];
    float* out = (float*)d_out;
    (void)in_sizes; (void)n_in; (void)out_size;

    k0_zero<<<(NATOMS * NATOMS + 255) / 256, 256>>>();
    k1_M<<<(PDIM * FDIM * FDIM + 255) / 256, 256>>>(Wq, Wk);
    k2_T<<<NROWS_TOTAL / 256, 256>>>(x);
    {
        dim3 grid(2, 2, GK / K3_KCHUNK);   // 2 x 2 x 72 = 288 blocks
        k3s_dot<<<grid, 256>>>();
    }
    k4b_close<<<NATOMS, NATOMS>>>();
    {
        dim3 grid(18, NATOMS);             // chunk x (column slot, guarded)
        k5x_exact<<<grid, 256>>>(x);
    }
    k4_softmax<<<NATOMS, NATOMS>>>();
    k5_compact<<<NATOMS, NATOMS>>>();
    {
        dim3 grid((NATOMS * PDIM * LDIM) / 256, NATOMS);   // 18 x 256
        k6_out<<<grid, 256>>>(x, Wv, out);
    }
}

// round 6
// speedup vs baseline: 1.0809x; 1.0809x over previous
#include <cuda_runtime.h>
#include <cuda_bf16.h>

#define NATOMS 256
#define PDIM 2
#define LDIM 9
#define FDIM 64
#define ROWLEN (PDIM*LDIM*FDIM)                 // 1152
#define GK (NATOMS*ROWLEN)                      // 294912
#define NROWS_TOTAL (NATOMS*NATOMS*PDIM*LDIM)   // 1,179,648 rows of 64

// ---------------- scratch (static device globals; no runtime alloc) ----------
__device__ __nv_bfloat16  g_Thi[NATOMS * GK];
__device__ __nv_bfloat16  g_Tlo[NATOMS * GK];
__device__ __nv_bfloat16  g_xhi[NATOMS * GK];
__device__ __nv_bfloat16  g_xlo[NATOMS * GK];
__device__ float          g_V  [NATOMS * GK];   // fp32 V = x @ Wv
__device__ float g_M[PDIM * FDIM * FDIM];       // fp32 M_p = Wq_p Wk_p^T (for k5x)
__device__ __nv_bfloat16 g_MtH[PDIM * FDIM * FDIM];   // Mt[p][f][e] hi
__device__ __nv_bfloat16 g_MtL[PDIM * FDIM * FDIM];   // Mt[p][f][e] lo
__device__ __nv_bfloat16 g_WvtH[PDIM * FDIM * FDIM];  // Wvt[p][f][e] hi
__device__ __nv_bfloat16 g_WvtL[PDIM * FDIM * FDIM];  // Wvt[p][f][e] lo
__device__ float g_dotb[NATOMS * NATOMS];
__device__ float g_w[NATOMS * NATOMS];
__device__ int   g_idx[NATOMS * NATOMS];
__device__ float g_wval[NATOMS * NATOMS];
__device__ int   g_nnz[NATOMS];
__device__ int   g_ccol[NATOMS];
__device__ int   g_calist[NATOMS * 8];
__device__ int   g_cak[NATOMS];
__device__ int   g_nccols;

// ---------------- K0 ----------------------------------------------------------
__global__ void k0_zero() {
    int i = blockIdx.x * blockDim.x + threadIdx.x;
    if (i < NATOMS * NATOMS) g_dotb[i] = 0.0f;
    if (i < NATOMS) g_nnz[i] = 0;
    if (i == 0) g_nccols = 0;
}

// ---------------- K1: M (fp32) + Mt/Wvt bf16 hi/lo transposed -----------------
__global__ void k1_M(const float* __restrict__ Wq, const float* __restrict__ Wk,
                     const float* __restrict__ Wv) {
    int id = blockIdx.x * blockDim.x + threadIdx.x;
    if (id >= PDIM * FDIM * FDIM) return;
    int p = id >> 12;
    int e = (id >> 6) & 63;
    int f = id & 63;
    const float* q = Wq + (p << 12) + (e << 6);
    const float* k = Wk + (p << 12) + (f << 6);
    float s = 0.0f;
#pragma unroll 16
    for (int g = 0; g < 64; g++) s += q[g] * k[g];
    g_M[id] = s;

    int tid = (p << 12) + (f << 6) + e;   // transposed index [p][f][e]
    __nv_bfloat16 sh = __float2bfloat16_rn(s);
    g_MtH[tid] = sh;
    g_MtL[tid] = __float2bfloat16_rn(s - __bfloat162float(sh));

    float wv = Wv[id];
    __nv_bfloat16 wh = __float2bfloat16_rn(wv);
    g_WvtH[tid] = wh;
    g_WvtL[tid] = __float2bfloat16_rn(wv - __bfloat162float(wh));
}

// ---------------- shared mma helpers ------------------------------------------
static __device__ __forceinline__ void cpa16(unsigned sdst, const void* gsrc) {
    asm volatile("cp.async.cg.shared.global [%0], [%1], 16;\n" :: "r"(sdst), "l"(gsrc));
}
static __device__ __forceinline__ void ldsm_x4(unsigned r[4], unsigned addr) {
    asm volatile("ldmatrix.sync.aligned.m8n8.x4.shared.b16 {%0,%1,%2,%3}, [%4];\n"
        : "=r"(r[0]), "=r"(r[1]), "=r"(r[2]), "=r"(r[3]) : "r"(addr));
}
static __device__ __forceinline__ void mma_bf16(float d[4], const unsigned a[4],
                                                const unsigned b0, const unsigned b1) {
    asm volatile("mma.sync.aligned.m16n8k16.row.col.f32.bf16.bf16.f32 "
        "{%0,%1,%2,%3},{%4,%5,%6,%7},{%8,%9},{%0,%1,%2,%3};\n"
        : "+f"(d[0]), "+f"(d[1]), "+f"(d[2]), "+f"(d[3])
        : "r"(a[0]), "r"(a[1]), "r"(a[2]), "r"(a[3]), "r"(b0), "r"(b1));
}
static __device__ __forceinline__ unsigned pack_hi2(float a, float b) {
    __nv_bfloat162 h2 = __floats2bfloat162_rn(a, b);
    return *reinterpret_cast<unsigned*>(&h2);
}

// ---------------- K2V: persistent tensor-core kernel --------------------------
// Per 128-row tile: convert x -> xhi/xlo (smem + global), then
//   T = x@M_p (both p, 3-term split), V = x@Wv_p (both p, 3-term split),
// per-row parity select at epilogue. B operands are Mt/Wvt[p][f][e] (col-major).
#define PB 72                       // smem pitch (bf16 elems) -> conflict-free ldsm
#define K2V_GRID 296
#define K2V_TILES (NROWS_TOTAL / 128)   // 9216

extern __shared__ __nv_bfloat16 sm2[];

__global__ __launch_bounds__(256, 2) void k2v(const float* __restrict__ x) {
    // smem layout: mtH, mtL, wvH, wvL: [128 rows(pf)][PB]; xtH, xtL: [128][PB]
    __nv_bfloat16* mtH = sm2;
    __nv_bfloat16* mtL = mtH + 128 * PB;
    __nv_bfloat16* wvH = mtL + 128 * PB;
    __nv_bfloat16* wvL = wvH + 128 * PB;
    __nv_bfloat16* xtH = wvL + 128 * PB;
    __nv_bfloat16* xtL = xtH + 128 * PB;

    const int t = threadIdx.x;
    const int warp = t >> 5, lane = t & 31;

    // one-time load of Mt/Wvt hi/lo into padded smem
    for (int i = t; i < 8192; i += 256) {
        int pf = i >> 6, e = i & 63;
        mtH[pf * PB + e] = g_MtH[i];
        mtL[pf * PB + e] = g_MtL[i];
        wvH[pf * PB + e] = g_WvtH[i];
        wvL[pf * PB + e] = g_WvtL[i];
    }

    const unsigned uxh = (unsigned)__cvta_generic_to_shared(xtH);
    const unsigned uxl = (unsigned)__cvta_generic_to_shared(xtL);
    const unsigned umh = (unsigned)__cvta_generic_to_shared(mtH);
    const unsigned uml = (unsigned)__cvta_generic_to_shared(mtL);
    const unsigned uwh = (unsigned)__cvta_generic_to_shared(wvH);
    const unsigned uwl = (unsigned)__cvta_generic_to_shared(wvL);

    const int rloc = t >> 1;           // 0..127
    const int eh   = (t & 1) * 32;     // 0 or 32

    for (int tile = blockIdx.x; tile < K2V_TILES; tile += K2V_GRID) {
        const int r0 = tile * 128;
        __syncthreads();   // protect smem x-tile reuse across iterations

        // ---- load x rows, split hi/lo, stash smem + global ----
        {
            const float* gx = x + (size_t)(r0 + rloc) * 64 + eh;
            unsigned hibuf[16], lobuf[16];
#pragma unroll
            for (int q = 0; q < 8; q++) {
                float4 v = *(const float4*)(gx + q * 4);
                __nv_bfloat16 hx = __float2bfloat16_rn(v.x);
                __nv_bfloat16 hy = __float2bfloat16_rn(v.y);
                __nv_bfloat16 hz = __float2bfloat16_rn(v.z);
                __nv_bfloat16 hw = __float2bfloat16_rn(v.w);
                unsigned h01 = pack_hi2(v.x, v.y), h23 = pack_hi2(v.z, v.w);
                unsigned l01 = pack_hi2(v.x - __bfloat162float(hx),
                                        v.y - __bfloat162float(hy));
                unsigned l23 = pack_hi2(v.z - __bfloat162float(hz),
                                        v.w - __bfloat162float(hw));
                hibuf[q * 2] = h01; hibuf[q * 2 + 1] = h23;
                lobuf[q * 2] = l01; lobuf[q * 2 + 1] = l23;
                *(unsigned*)(xtH + rloc * PB + eh + q * 4)     = h01;
                *(unsigned*)(xtH + rloc * PB + eh + q * 4 + 2) = h23;
                *(unsigned*)(xtL + rloc * PB + eh + q * 4)     = l01;
                *(unsigned*)(xtL + rloc * PB + eh + q * 4 + 2) = l23;
            }
            uint4* dh = (uint4*)(g_xhi + (size_t)(r0 + rloc) * 64 + eh);
            uint4* dl = (uint4*)(g_xlo + (size_t)(r0 + rloc) * 64 + eh);
#pragma unroll
            for (int q = 0; q < 4; q++) {
                dh[q] = make_uint4(hibuf[4*q], hibuf[4*q+1], hibuf[4*q+2], hibuf[4*q+3]);
                dl[q] = make_uint4(lobuf[4*q], lobuf[4*q+1], lobuf[4*q+2], lobuf[4*q+3]);
            }
        }
        __syncthreads();

        const int rowbase = warp * 16;
        const unsigned axoff = ((rowbase + (lane & 15)) * PB + (lane >> 4) * 8) * 2;
        const int ra = rowbase + (lane >> 2);
        const int rb = ra + 8;
        const int pa = ((r0 + ra) / LDIM) & 1;
        const int pb = ((r0 + rb) / LDIM) & 1;
        const int lc = (lane & 3) * 2;

        // ================= phase T (B = Mt) =================
        {
            float acc[16][4];
#pragma unroll
            for (int n = 0; n < 16; n++)
#pragma unroll
                for (int v = 0; v < 4; v++) acc[n][v] = 0.0f;

#pragma unroll
            for (int k = 0; k < 4; k++) {
                unsigned Ah[4], Al[4];
                ldsm_x4(Ah, uxh + axoff + k * 32);   // k*16 elems = 32 bytes
                ldsm_x4(Al, uxl + axoff + k * 32);
#pragma unroll
                for (int n2 = 0; n2 < 8; n2++) {
                    unsigned B[4];
                    ldsm_x4(B, umh + (((n2 * 16) + (lane & 15)) * PB + (lane >> 4) * 8) * 2 + k * 32);
                    mma_bf16(acc[2*n2],   Ah, B[0], B[2]);
                    mma_bf16(acc[2*n2+1], Ah, B[1], B[3]);
                    mma_bf16(acc[2*n2],   Al, B[0], B[2]);
                    mma_bf16(acc[2*n2+1], Al, B[1], B[3]);
                }
#pragma unroll
                for (int n2 = 0; n2 < 8; n2++) {
                    unsigned B[4];
                    ldsm_x4(B, uml + (((n2 * 16) + (lane & 15)) * PB + (lane >> 4) * 8) * 2 + k * 32);
                    mma_bf16(acc[2*n2],   Ah, B[0], B[2]);
                    mma_bf16(acc[2*n2+1], Ah, B[1], B[3]);
                }
            }
            // epilogue: per-row parity select, hi/lo bf16 out
            __nv_bfloat16* thA = g_Thi + (size_t)(r0 + ra) * 64;
            __nv_bfloat16* tlA = g_Tlo + (size_t)(r0 + ra) * 64;
            __nv_bfloat16* thB = g_Thi + (size_t)(r0 + rb) * 64;
            __nv_bfloat16* tlB = g_Tlo + (size_t)(r0 + rb) * 64;
#pragma unroll
            for (int j = 0; j < 8; j++) {
                float a0 = acc[pa*8+j][0], a1 = acc[pa*8+j][1];
                float b0 = acc[pb*8+j][2], b1 = acc[pb*8+j][3];
                __nv_bfloat16 a0h = __float2bfloat16_rn(a0);
                __nv_bfloat16 a1h = __float2bfloat16_rn(a1);
                __nv_bfloat16 b0h = __float2bfloat16_rn(b0);
                __nv_bfloat16 b1h = __float2bfloat16_rn(b1);
                int col = j * 8 + lc;
                *(unsigned*)(thA + col) = pack_hi2(a0, a1);
                *(unsigned*)(tlA + col) = pack_hi2(a0 - __bfloat162float(a0h),
                                                   a1 - __bfloat162float(a1h));
                *(unsigned*)(thB + col) = pack_hi2(b0, b1);
                *(unsigned*)(tlB + col) = pack_hi2(b0 - __bfloat162float(b0h),
                                                   b1 - __bfloat162float(b1h));
            }
        }

        // ================= phase V (B = Wvt), fp32 out =================
        {
            float acc[16][4];
#pragma unroll
            for (int n = 0; n < 16; n++)
#pragma unroll
                for (int v = 0; v < 4; v++) acc[n][v] = 0.0f;

#pragma unroll
            for (int k = 0; k < 4; k++) {
                unsigned Ah[4], Al[4];
                ldsm_x4(Ah, uxh + axoff + k * 32);
                ldsm_x4(Al, uxl + axoff + k * 32);
#pragma unroll
                for (int n2 = 0; n2 < 8; n2++) {
                    unsigned B[4];
                    ldsm_x4(B, uwh + (((n2 * 16) + (lane & 15)) * PB + (lane >> 4) * 8) * 2 + k * 32);
                    mma_bf16(acc[2*n2],   Ah, B[0], B[2]);
                    mma_bf16(acc[2*n2+1], Ah, B[1], B[3]);
                    mma_bf16(acc[2*n2],   Al, B[0], B[2]);
                    mma_bf16(acc[2*n2+1], Al, B[1], B[3]);
                }
#pragma unroll
                for (int n2 = 0; n2 < 8; n2++) {
                    unsigned B[4];
                    ldsm_x4(B, uwl + (((n2 * 16) + (lane & 15)) * PB + (lane >> 4) * 8) * 2 + k * 32);
                    mma_bf16(acc[2*n2],   Ah, B[0], B[2]);
                    mma_bf16(acc[2*n2+1], Ah, B[1], B[3]);
                }
            }
            float* vA = g_V + (size_t)(r0 + ra) * 64;
            float* vB = g_V + (size_t)(r0 + rb) * 64;
#pragma unroll
            for (int j = 0; j < 8; j++) {
                int col = j * 8 + lc;
                *(float2*)(vA + col) = make_float2(acc[pa*8+j][0], acc[pa*8+j][1]);
                *(float2*)(vB + col) = make_float2(acc[pb*8+j][2], acc[pb*8+j][3]);
            }
        }
    }
}

// ---------------- K3s: dotb = Thi*xhi^T + Thi*xlo^T + Tlo*xhi^T ---------------
#define K3_KCHUNK 4096
#define PITCH 16
#define STAGE_BYTES (128 * PITCH * 2)   // 4096

__global__ __launch_bounds__(256, 2) void k3s_dot() {
    __shared__ __nv_bfloat16 Ah[3][128 * PITCH];
    __shared__ __nv_bfloat16 Al[3][128 * PITCH];
    __shared__ __nv_bfloat16 Bh[3][128 * PITCH];
    __shared__ __nv_bfloat16 Bl[3][128 * PITCH];
    const int t = threadIdx.x;
    const int m0 = blockIdx.x * 128, n0 = blockIdx.y * 128;
    const size_t kb = (size_t)blockIdx.z * K3_KCHUNK;

    const unsigned uAh = (unsigned)__cvta_generic_to_shared(&Ah[0][0]);
    const unsigned uAl = (unsigned)__cvta_generic_to_shared(&Al[0][0]);
    const unsigned uBh = (unsigned)__cvta_generic_to_shared(&Bh[0][0]);
    const unsigned uBl = (unsigned)__cvta_generic_to_shared(&Bl[0][0]);

    const int row = t >> 1, half = t & 1;
    const size_t goff = (size_t)row * GK + kb + half * 8;
    const __nv_bfloat16* gah = g_Thi + (size_t)m0 * GK + goff;
    const __nv_bfloat16* gal = g_Tlo + (size_t)m0 * GK + goff;
    const __nv_bfloat16* gbh = g_xhi + (size_t)n0 * GK + goff;
    const __nv_bfloat16* gbl = g_xlo + (size_t)n0 * GK + goff;
    const unsigned soff = (row * PITCH + half * 8) * 2;

    const int NS = K3_KCHUNK / 16;

#pragma unroll
    for (int s = 0; s < 2; s++) {
        cpa16(uAh + soff + s * STAGE_BYTES, gah + (size_t)s * 16);
        cpa16(uAl + soff + s * STAGE_BYTES, gal + (size_t)s * 16);
        cpa16(uBh + soff + s * STAGE_BYTES, gbh + (size_t)s * 16);
        cpa16(uBl + soff + s * STAGE_BYTES, gbl + (size_t)s * 16);
        asm volatile("cp.async.commit_group;\n");
    }

    const int warp = t >> 5, lane = t & 31;
    const int wm = warp >> 2, wn = warp & 3;
    const unsigned aoff = ((wm * 64 + (lane & 15)) * PITCH + (lane >> 4) * 8) * 2;
    const unsigned boff = ((wn * 32 + (lane & 15)) * PITCH + (lane >> 4) * 8) * 2;

    float acc[4][4][4] = {};

    int buf = 0, pbuf = 2;
    for (int ks = 0; ks < NS; ks++) {
        asm volatile("cp.async.wait_group %0;\n" :: "n"(1));
        __syncthreads();

        unsigned bh[2][4], bl[2][4];
#pragma unroll
        for (int j = 0; j < 2; j++) {
            ldsm_x4(bh[j], uBh + boff + buf * STAGE_BYTES + j * 16 * PITCH * 2);
            ldsm_x4(bl[j], uBl + boff + buf * STAGE_BYTES + j * 16 * PITCH * 2);
        }
        // i-pairs, term-outer: same-acc mma distance = 8
#pragma unroll
        for (int ip = 0; ip < 2; ip++) {
            unsigned a0h[4], a0l[4], a1h[4], a1l[4];
            ldsm_x4(a0h, uAh + aoff + buf * STAGE_BYTES + (2*ip)   * 16 * PITCH * 2);
            ldsm_x4(a0l, uAl + aoff + buf * STAGE_BYTES + (2*ip)   * 16 * PITCH * 2);
            ldsm_x4(a1h, uAh + aoff + buf * STAGE_BYTES + (2*ip+1) * 16 * PITCH * 2);
            ldsm_x4(a1l, uAl + aoff + buf * STAGE_BYTES + (2*ip+1) * 16 * PITCH * 2);
#pragma unroll
            for (int j = 0; j < 4; j++) {   // term hh
                unsigned b0 = bh[j >> 1][(j & 1)], b1 = bh[j >> 1][(j & 1) + 2];
                mma_bf16(acc[2*ip][j],   a0h, b0, b1);
                mma_bf16(acc[2*ip+1][j], a1h, b0, b1);
            }
#pragma unroll
            for (int j = 0; j < 4; j++) {   // term hl
                unsigned b0 = bl[j >> 1][(j & 1)], b1 = bl[j >> 1][(j & 1) + 2];
                mma_bf16(acc[2*ip][j],   a0h, b0, b1);
                mma_bf16(acc[2*ip+1][j], a1h, b0, b1);
            }
#pragma unroll
            for (int j = 0; j < 4; j++) {   // term lh
                unsigned b0 = bh[j >> 1][(j & 1)], b1 = bh[j >> 1][(j & 1) + 2];
                mma_bf16(acc[2*ip][j],   a0l, b0, b1);
                mma_bf16(acc[2*ip+1][j], a1l, b0, b1);
            }
        }

        const int pf = ks + 2;
        if (pf < NS) {
            cpa16(uAh + soff + pbuf * STAGE_BYTES, gah + (size_t)pf * 16);
            cpa16(uAl + soff + pbuf * STAGE_BYTES, gal + (size_t)pf * 16);
            cpa16(uBh + soff + pbuf * STAGE_BYTES, gbh + (size_t)pf * 16);
            cpa16(uBl + soff + pbuf * STAGE_BYTES, gbl + (size_t)pf * 16);
        }
        asm volatile("cp.async.commit_group;\n");
        buf = (buf == 2) ? 0 : buf + 1;
        pbuf = (pbuf == 2) ? 0 : pbuf + 1;
    }
    asm volatile("cp.async.wait_group 0;\n");

    const int lr = lane >> 2, lc = (lane & 3) * 2;
#pragma unroll
    for (int i = 0; i < 4; i++)
#pragma unroll
        for (int j = 0; j < 4; j++) {
            int r = m0 + wm * 64 + i * 16 + lr;
            int c = n0 + wn * 32 + j * 8 + lc;
            atomicAdd(&g_dotb[r * NATOMS + c],           acc[i][j][0]);
            atomicAdd(&g_dotb[r * NATOMS + c + 1],       acc[i][j][1]);
            atomicAdd(&g_dotb[(r + 8) * NATOMS + c],     acc[i][j][2]);
            atomicAdd(&g_dotb[(r + 8) * NATOMS + c + 1], acc[i][j][3]);
        }
}

// ---------------- K4b: columns with >=2 entries within margin ----------------
#define CLOSE_MARGIN 14.0f
__global__ void k4b_close() {
    int c = blockIdx.x, t = threadIdx.x;
    __shared__ float red[256];
    __shared__ int cnt, pos;
    if (t == 0) { cnt = 0; pos = 0; }
    float v = g_dotb[t * NATOMS + c];
    red[t] = v; __syncthreads();
    for (int s = 128; s > 0; s >>= 1) {
        if (t < s) red[t] = fmaxf(red[t], red[t + s]);
        __syncthreads();
    }
    float mx = red[0];
    bool cand = (v >= mx - CLOSE_MARGIN);
    if (cand) atomicAdd(&cnt, 1);
    __syncthreads();
    if (cnt >= 2) {
        if (t == 0) { int s = atomicAdd(&g_nccols, 1); g_ccol[s] = c; }
        if (cand) {
            int p = atomicAdd(&pos, 1);
            if (p < 8) { g_calist[c * 8 + p] = t; g_dotb[t * NATOMS + c] = 0.0f; }
        }
        __syncthreads();
        if (t == 0) g_cak[c] = (cnt < 8) ? cnt : 8;
    }
}

// ---------------- K5x: exact fp32 logits for close columns -------------------
__global__ __launch_bounds__(256) void k5x_exact(const float* __restrict__ x) {
    __shared__ float Msh[2 * 4096];
    __shared__ float red[256];
    int s = blockIdx.y;
    if (s >= g_nccols) return;
    int t = threadIdx.x;
    int c = g_ccol[s];
    int ka = g_cak[c];

    for (int i = t; i < 8192 / 4; i += 256)
        ((float4*)Msh)[i] = ((const float4*)g_M)[i];
    __syncthreads();

    int row = blockIdx.x * 256 + t;
    int p = (row / LDIM) & 1;
    const float* Mp = Msh + (p << 12);

    float xc[64];
    {
        const float4* xcp = (const float4*)(x + (size_t)c * GK + (size_t)row * 64);
#pragma unroll
        for (int i = 0; i < 16; i++) {
            float4 v = xcp[i];
            xc[4*i] = v.x; xc[4*i+1] = v.y; xc[4*i+2] = v.z; xc[4*i+3] = v.w;
        }
    }
    float z[64];
#pragma unroll 4
    for (int e = 0; e < 64; e++) {
        const float4* Mr = (const float4*)(Mp + e * 64);
        float sm = 0.0f;
#pragma unroll
        for (int f4 = 0; f4 < 16; f4++) {
            float4 m = Mr[f4];
            sm += m.x * xc[4*f4] + m.y * xc[4*f4+1] + m.z * xc[4*f4+2] + m.w * xc[4*f4+3];
        }
        z[e] = sm;
    }

    for (int j = 0; j < ka; j++) {
        int a = g_calist[c * 8 + j];
        const float4* xap = (const float4*)(x + (size_t)a * GK + (size_t)row * 64);
        float sd = 0.0f;
#pragma unroll
        for (int i = 0; i < 16; i++) {
            float4 v = xap[i];
            sd += v.x * z[4*i] + v.y * z[4*i+1] + v.z * z[4*i+2] + v.w * z[4*i+3];
        }
        red[t] = sd; __syncthreads();
        for (int st = 128; st > 0; st >>= 1) {
            if (t < st) red[t] += red[t + st];
            __syncthreads();
        }
        if (t == 0) atomicAdd(&g_dotb[a * NATOMS + c], red[0]);
        __syncthreads();
    }
}

// ---------------- K4: softmax over axis a -------------------------------------
__global__ void k4_softmax() {
    int c = blockIdx.x, t = threadIdx.x;
    __shared__ float red[256];
    float v = g_dotb[t * NATOMS + c];
    red[t] = v; __syncthreads();
    for (int s = 128; s > 0; s >>= 1) {
        if (t < s) red[t] = fmaxf(red[t], red[t + s]);
        __syncthreads();
    }
    float mx = red[0]; __syncthreads();
    float e = expf(v - mx);
    red[t] = e; __syncthreads();
    for (int s = 128; s > 0; s >>= 1) {
        if (t < s) red[t] += red[t + s];
        __syncthreads();
    }
    g_w[t * NATOMS + c] = e / red[0];
}

// ---------------- K5: compact significant weights -----------------------------
__global__ void k5_compact() {
    int a = blockIdx.x, t = threadIdx.x;
    float wv = g_w[a * NATOMS + t];
    bool nz = (wv > 1e-7f);
    unsigned m = __ballot_sync(0xffffffffu, nz);
    int lane = t & 31, warp = t >> 5;
    int pre = __popc(m & ((1u << lane) - 1u));
    __shared__ int wcnt[8], woff[8];
    if (lane == 0) wcnt[warp] = __popc(m);
    __syncthreads();
    if (t == 0) {
        int s = 0;
        for (int i = 0; i < 8; i++) { woff[i] = s; s += wcnt[i]; }
        g_nnz[a] = s;
    }
    __syncthreads();
    if (nz) {
        int pos = woff[warp] + pre;
        g_idx[a * NATOMS + pos]  = t;
        g_wval[a * NATOMS + pos] = wv;
    }
}

// ---------------- K6V: out[a] = sum_j w_j * V[b_j]  (pure gather-AXPY) --------
__global__ __launch_bounds__(256, 4) void k6v(float* __restrict__ out) {
    __shared__ float wlist[NATOMS];
    __shared__ int   blist[NATOMS];
    __shared__ int   s_nnz;
    int t = threadIdx.x;
    int a = blockIdx.y;
    int r0 = blockIdx.x * 256;

    if (t == 0) s_nnz = g_nnz[a];
    __syncthreads();
    int nnz = s_nnz;

    int rowt = t >> 4;
    int e4   = (t & 15) * 4;

    if (nnz == 0) {
        float4 z = make_float4(0.f, 0.f, 0.f, 0.f);
#pragma unroll
        for (int i = 0; i < 16; i++) {
            int row = i * 16 + rowt;
            *(float4*)(out + (size_t)a * GK + (size_t)(r0 + row) * 64 + e4) = z;
        }
        return;
    }
    if (t < nnz) { blist[t] = g_idx[a * NATOMS + t]; wlist[t] = g_wval[a * NATOMS + t]; }
    __syncthreads();

#pragma unroll 2
    for (int i = 0; i < 16; i++) {
        int row = i * 16 + rowt;
        size_t off = (size_t)(r0 + row) * 64 + e4;
        float ax = 0.f, ay = 0.f, az = 0.f, aw = 0.f;
        int j = 0;
        for (; j + 1 < nnz; j += 2) {
            const float4 v0 = *(const float4*)(g_V + (size_t)blist[j]   * GK + off);
            const float4 v1 = *(const float4*)(g_V + (size_t)blist[j+1] * GK + off);
            float w0 = wlist[j], w1 = wlist[j+1];
            ax += w0*v0.x + w1*v1.x; ay += w0*v0.y + w1*v1.y;
            az += w0*v0.z + w1*v1.z; aw += w0*v0.w + w1*v1.w;
        }
        if (j < nnz) {
            const float4 v0 = *(const float4*)(g_V + (size_t)blist[j] * GK + off);
            float w0 = wlist[j];
            ax += w0*v0.x; ay += w0*v0.y; az += w0*v0.z; aw += w0*v0.w;
        }
        *(float4*)(out + (size_t)a * GK + off) = make_float4(ax, ay, az, aw);
    }
}

// ---------------- launch -------------------------------------------------------
extern "C" void kernel_launch(void* const* d_in, const int* in_sizes, int n_in,
                              void* d_out, int out_size) {
    const float* x  = (const float*)d_in[0];
    const float* Wq = (const float*)d_in[1];
    const float* Wk = (const float*)d_in[2];
    const float* Wv = (const float*)d_in[3];
    float* out = (float*)d_out;
    (void)in_sizes; (void)n_in; (void)out_size;

    const int k2v_smem = 6 * 128 * PB * 2;   // 110,592 bytes
    cudaFuncSetAttribute(k2v, cudaFuncAttributeMaxDynamicSharedMemorySize, k2v_smem);

    k0_zero<<<(NATOMS * NATOMS + 255) / 256, 256>>>();
    k1_M<<<(PDIM * FDIM * FDIM + 255) / 256, 256>>>(Wq, Wk, Wv);
    k2v<<<K2V_GRID, 256, k2v_smem>>>(x);
    {
        dim3 grid(2, 2, GK / K3_KCHUNK);
        k3s_dot<<<grid, 256>>>();
    }
    k4b_close<<<NATOMS, NATOMS>>>();
    {
        dim3 grid(18, NATOMS);
        k5x_exact<<<grid, 256>>>(x);
    }
    k4_softmax<<<NATOMS, NATOMS>>>();
    k5_compact<<<NATOMS, NATOMS>>>();
    {
        dim3 grid((NATOMS * PDIM * LDIM) / 256, NATOMS);
        k6v<<<grid, 256>>>(out);
    }
}

// round 7
// speedup vs baseline: 2.5281x; 2.3389x over previous
#include <cuda_runtime.h>
#include <cuda_bf16.h>

#define NATOMS 256
#define PDIM 2
#define LDIM 9
#define FDIM 64
#define ROWLEN (PDIM*LDIM*FDIM)                 // 1152
#define GK (NATOMS*ROWLEN)                      // 294912
#define NROWS_TOTAL (NATOMS*NATOMS*PDIM*LDIM)   // 1,179,648 rows of 64
#define HROWS (NROWS_TOTAL/2)                   // rows per parity

// ---------------- scratch ------------------------------------------------------
__device__ __nv_bfloat16  g_Thi[NATOMS * GK];
__device__ __nv_bfloat16  g_Tlo[NATOMS * GK];
__device__ __nv_bfloat16  g_xhi[NATOMS * GK];
__device__ float          g_V  [NATOMS * GK];
__device__ float g_M[PDIM * FDIM * FDIM];
__device__ __nv_bfloat16 g_MtH[PDIM * FDIM * FDIM];
__device__ __nv_bfloat16 g_MtL[PDIM * FDIM * FDIM];
__device__ __nv_bfloat16 g_WvtH[PDIM * FDIM * FDIM];
__device__ __nv_bfloat16 g_WvtL[PDIM * FDIM * FDIM];
__device__ float g_dotb[NATOMS * NATOMS];
__device__ float g_w[NATOMS * NATOMS];
__device__ int   g_idx[NATOMS * NATOMS];
__device__ float g_wval[NATOMS * NATOMS];
__device__ int   g_nnz[NATOMS];
__device__ int   g_ccol[NATOMS];
__device__ int   g_calist[NATOMS * 8];
__device__ int   g_cak[NATOMS];
__device__ int   g_nccols;

extern __shared__ __nv_bfloat16 smdyn[];

// ---------------- K0 ------------------------------------------------------------
__global__ void k0_zero() {
    int i = blockIdx.x * blockDim.x + threadIdx.x;
    if (i < NATOMS * NATOMS) g_dotb[i] = 0.0f;
    if (i < NATOMS) g_nnz[i] = 0;
    if (i == 0) g_nccols = 0;
}

// ---------------- K1 ------------------------------------------------------------
__global__ void k1_M(const float* __restrict__ Wq, const float* __restrict__ Wk,
                     const float* __restrict__ Wv) {
    int id = blockIdx.x * blockDim.x + threadIdx.x;
    if (id >= PDIM * FDIM * FDIM) return;
    int p = id >> 12;
    int e = (id >> 6) & 63;
    int f = id & 63;
    const float* q = Wq + (p << 12) + (e << 6);
    const float* k = Wk + (p << 12) + (f << 6);
    float s = 0.0f;
#pragma unroll 16
    for (int g = 0; g < 64; g++) s += q[g] * k[g];
    g_M[id] = s;

    int tid = (p << 12) + (f << 6) + e;   // transposed [p][f][e]
    __nv_bfloat16 sh = __float2bfloat16_rn(s);
    g_MtH[tid] = sh;
    g_MtL[tid] = __float2bfloat16_rn(s - __bfloat162float(sh));

    float wv = Wv[id];
    __nv_bfloat16 wh = __float2bfloat16_rn(wv);
    g_WvtH[tid] = wh;
    g_WvtL[tid] = __float2bfloat16_rn(wv - __bfloat162float(wh));
}

// ---------------- helpers --------------------------------------------------------
static __device__ __forceinline__ void cpa16(unsigned sdst, const void* gsrc) {
    asm volatile("cp.async.cg.shared.global [%0], [%1], 16;\n" :: "r"(sdst), "l"(gsrc));
}
static __device__ __forceinline__ void ldsm_x4(unsigned r[4], unsigned addr) {
    asm volatile("ldmatrix.sync.aligned.m8n8.x4.shared.b16 {%0,%1,%2,%3}, [%4];\n"
        : "=r"(r[0]), "=r"(r[1]), "=r"(r[2]), "=r"(r[3]) : "r"(addr));
}
static __device__ __forceinline__ void mma_bf16(float d[4], const unsigned a[4],
                                                const unsigned b0, const unsigned b1) {
    asm volatile("mma.sync.aligned.m16n8k16.row.col.f32.bf16.bf16.f32 "
        "{%0,%1,%2,%3},{%4,%5,%6,%7},{%8,%9},{%0,%1,%2,%3};\n"
        : "+f"(d[0]), "+f"(d[1]), "+f"(d[2]), "+f"(d[3])
        : "r"(a[0]), "r"(a[1]), "r"(a[2]), "r"(a[3]), "r"(b0), "r"(b1));
}
static __device__ __forceinline__ unsigned pack_hi2(float a, float b) {
    __nv_bfloat162 h2 = __floats2bfloat162_rn(a, b);
    return *reinterpret_cast<unsigned*>(&h2);
}
static __device__ __forceinline__ unsigned pack_lo2(float a, float b) {
    float ra = a - __bfloat162float(__float2bfloat16_rn(a));
    float rb = b - __bfloat162float(__float2bfloat16_rn(b));
    __nv_bfloat162 h2 = __floats2bfloat162_rn(ra, rb);
    return *reinterpret_cast<unsigned*>(&h2);
}

// ---------------- K2V: parity-sorted tensor-core T/V + xhi emit ------------------
// Block handles 128 rows of ONE parity: local i -> global row q*18 + P*9 + l,
// with g = blockIdx.x*128 + i, q = g/9, l = g%9, P = blockIdx.y.
#define PB 72   // smem pitch (bf16): 144B rows -> conflict-free ldsm

__global__ __launch_bounds__(256, 2) void k2v(const float* __restrict__ x) {
    // carve: mtH,mtL,wvH,wvL: [64][PB]; xtH,xtL: [128][PB]
    __nv_bfloat16* mtH = smdyn;
    __nv_bfloat16* mtL = mtH + 64 * PB;
    __nv_bfloat16* wvH = mtL + 64 * PB;
    __nv_bfloat16* wvL = wvH + 64 * PB;
    __nv_bfloat16* xtH = wvL + 64 * PB;
    __nv_bfloat16* xtL = xtH + 128 * PB;

    const int t = threadIdx.x;
    const int warp = t >> 5, lane = t & 31;
    const int P = blockIdx.y;
    const int r0 = blockIdx.x * 128;      // parity-local row base

    // load single-parity weights (hi/lo, transposed [f][e]) into padded smem
    for (int i = t; i < 4096; i += 256) {
        int f = i >> 6, e = i & 63;
        int src = (P << 12) + i;
        mtH[f * PB + e] = g_MtH[src];
        mtL[f * PB + e] = g_MtL[src];
        wvH[f * PB + e] = g_WvtH[src];
        wvL[f * PB + e] = g_WvtL[src];
    }

    // stage x rows (2 threads/row), split hi/lo; emit xhi to global
    const int rloc = t >> 1;
    const int eh   = (t & 1) * 32;
    {
        int g = r0 + rloc;
        int q = g / 9, l = g - 9 * q;
        size_t gr = (size_t)(q * 18 + P * 9 + l);
        const float* gx = x + gr * 64 + eh;
        unsigned hibuf[16];
#pragma unroll
        for (int qq = 0; qq < 8; qq++) {
            float4 v = *(const float4*)(gx + qq * 4);
            unsigned h01 = pack_hi2(v.x, v.y), h23 = pack_hi2(v.z, v.w);
            unsigned l01 = pack_lo2(v.x, v.y), l23 = pack_lo2(v.z, v.w);
            hibuf[qq * 2] = h01; hibuf[qq * 2 + 1] = h23;
            *(unsigned*)(xtH + rloc * PB + eh + qq * 4)     = h01;
            *(unsigned*)(xtH + rloc * PB + eh + qq * 4 + 2) = h23;
            *(unsigned*)(xtL + rloc * PB + eh + qq * 4)     = l01;
            *(unsigned*)(xtL + rloc * PB + eh + qq * 4 + 2) = l23;
        }
        uint4* dh = (uint4*)(g_xhi + gr * 64 + eh);
#pragma unroll
        for (int qq = 0; qq < 4; qq++)
            dh[qq] = make_uint4(hibuf[4*qq], hibuf[4*qq+1], hibuf[4*qq+2], hibuf[4*qq+3]);
    }
    __syncthreads();

    const unsigned uxh = (unsigned)__cvta_generic_to_shared(xtH);
    const unsigned uxl = (unsigned)__cvta_generic_to_shared(xtL);
    const unsigned umh = (unsigned)__cvta_generic_to_shared(mtH);
    const unsigned uml = (unsigned)__cvta_generic_to_shared(mtL);
    const unsigned uwh = (unsigned)__cvta_generic_to_shared(wvH);
    const unsigned uwl = (unsigned)__cvta_generic_to_shared(wvL);

    const int rowbase = warp * 16;
    const unsigned axoff = ((rowbase + (lane & 15)) * PB + (lane >> 4) * 8) * 2;
    const int lc = (lane & 3) * 2;

    // global rows for epilogue (fragment rows ra, ra+8)
    const int raL = rowbase + (lane >> 2);
    size_t graA, graB;
    {
        int g = r0 + raL;      int q = g / 9, l = g - 9 * q;
        graA = (size_t)(q * 18 + P * 9 + l);
        g += 8;                q = g / 9; l = g - 9 * q;
        graB = (size_t)(q * 18 + P * 9 + l);
    }

    // ---- phase T (B = Mt hi/lo, 3-term) ----
    {
        float acc[8][4];
#pragma unroll
        for (int n = 0; n < 8; n++)
#pragma unroll
            for (int v = 0; v < 4; v++) acc[n][v] = 0.0f;

#pragma unroll
        for (int k = 0; k < 4; k++) {
            unsigned Ah[4], Al[4];
            ldsm_x4(Ah, uxh + axoff + k * 32);
            ldsm_x4(Al, uxl + axoff + k * 32);
#pragma unroll
            for (int n2 = 0; n2 < 4; n2++) {
                unsigned bo = ((n2 * 16 + (lane & 15)) * PB + (lane >> 4) * 8) * 2 + k * 32;
                unsigned Bh[4], Bl[4];
                ldsm_x4(Bh, umh + bo);
                mma_bf16(acc[2*n2],   Ah, Bh[0], Bh[2]);
                mma_bf16(acc[2*n2+1], Ah, Bh[1], Bh[3]);
                mma_bf16(acc[2*n2],   Al, Bh[0], Bh[2]);
                mma_bf16(acc[2*n2+1], Al, Bh[1], Bh[3]);
                ldsm_x4(Bl, uml + bo);
                mma_bf16(acc[2*n2],   Ah, Bl[0], Bl[2]);
                mma_bf16(acc[2*n2+1], Ah, Bl[1], Bl[3]);
            }
        }
        __nv_bfloat16* thA = g_Thi + graA * 64;
        __nv_bfloat16* tlA = g_Tlo + graA * 64;
        __nv_bfloat16* thB = g_Thi + graB * 64;
        __nv_bfloat16* tlB = g_Tlo + graB * 64;
#pragma unroll
        for (int n = 0; n < 8; n++) {
            int col = n * 8 + lc;
            *(unsigned*)(thA + col) = pack_hi2(acc[n][0], acc[n][1]);
            *(unsigned*)(tlA + col) = pack_lo2(acc[n][0], acc[n][1]);
            *(unsigned*)(thB + col) = pack_hi2(acc[n][2], acc[n][3]);
            *(unsigned*)(tlB + col) = pack_lo2(acc[n][2], acc[n][3]);
        }
    }

    // ---- phase V (B = Wvt hi/lo, 3-term), fp32 out ----
    {
        float acc[8][4];
#pragma unroll
        for (int n = 0; n < 8; n++)
#pragma unroll
            for (int v = 0; v < 4; v++) acc[n][v] = 0.0f;

#pragma unroll
        for (int k = 0; k < 4; k++) {
            unsigned Ah[4], Al[4];
            ldsm_x4(Ah, uxh + axoff + k * 32);
            ldsm_x4(Al, uxl + axoff + k * 32);
#pragma unroll
            for (int n2 = 0; n2 < 4; n2++) {
                unsigned bo = ((n2 * 16 + (lane & 15)) * PB + (lane >> 4) * 8) * 2 + k * 32;
                unsigned Bh[4], Bl[4];
                ldsm_x4(Bh, uwh + bo);
                mma_bf16(acc[2*n2],   Ah, Bh[0], Bh[2]);
                mma_bf16(acc[2*n2+1], Ah, Bh[1], Bh[3]);
                mma_bf16(acc[2*n2],   Al, Bh[0], Bh[2]);
                mma_bf16(acc[2*n2+1], Al, Bh[1], Bh[3]);
                ldsm_x4(Bl, uwl + bo);
                mma_bf16(acc[2*n2],   Ah, Bl[0], Bl[2]);
                mma_bf16(acc[2*n2+1], Ah, Bl[1], Bl[3]);
            }
        }
        float* vA = g_V + graA * 64;
        float* vB = g_V + graB * 64;
#pragma unroll
        for (int n = 0; n < 8; n++) {
            int col = n * 8 + lc;
            *(float2*)(vA + col) = make_float2(acc[n][0], acc[n][1]);
            *(float2*)(vB + col) = make_float2(acc[n][2], acc[n][3]);
        }
    }
}

// ---------------- K3s: dotb = (Thi+Tlo) * xhi^T  (2-term, conflict-free) ---------
#define K3_KCHUNK 4096
#define PITCH 24                         // 48B rows: conflict-free ldsm
#define STAGE_BYTES (128 * PITCH * 2)    // 6144
#define STAGE_ELEMS (128 * PITCH)

__global__ __launch_bounds__(256, 2) void k3s_dot() {
    __nv_bfloat16* Ah = smdyn;                    // [3][STAGE_ELEMS]
    __nv_bfloat16* Al = Ah + 3 * STAGE_ELEMS;
    __nv_bfloat16* Bh = Al + 3 * STAGE_ELEMS;

    const int t = threadIdx.x;
    const int m0 = blockIdx.x * 128, n0 = blockIdx.y * 128;
    const size_t kb = (size_t)blockIdx.z * K3_KCHUNK;

    const unsigned uAh = (unsigned)__cvta_generic_to_shared(Ah);
    const unsigned uAl = (unsigned)__cvta_generic_to_shared(Al);
    const unsigned uBh = (unsigned)__cvta_generic_to_shared(Bh);

    const int row = t >> 1, half = t & 1;
    const size_t goff = (size_t)row * GK + kb + half * 8;
    const __nv_bfloat16* gah = g_Thi + (size_t)m0 * GK + goff;
    const __nv_bfloat16* gal = g_Tlo + (size_t)m0 * GK + goff;
    const __nv_bfloat16* gbh = g_xhi + (size_t)n0 * GK + goff;
    const unsigned soff = (row * PITCH + half * 8) * 2;

    const int NS = K3_KCHUNK / 16;

#pragma unroll
    for (int s = 0; s < 2; s++) {
        cpa16(uAh + soff + s * STAGE_BYTES, gah + (size_t)s * 16);
        cpa16(uAl + soff + s * STAGE_BYTES, gal + (size_t)s * 16);
        cpa16(uBh + soff + s * STAGE_BYTES, gbh + (size_t)s * 16);
        asm volatile("cp.async.commit_group;\n");
    }

    const int warp = t >> 5, lane = t & 31;
    const int wm = warp >> 2, wn = warp & 3;
    const unsigned aoff = ((wm * 64 + (lane & 15)) * PITCH + (lane >> 4) * 8) * 2;
    const unsigned boff = ((wn * 32 + (lane & 15)) * PITCH + (lane >> 4) * 8) * 2;

    float acc[4][4][4] = {};

    int buf = 0, pbuf = 2;
    for (int ks = 0; ks < NS; ks++) {
        asm volatile("cp.async.wait_group %0;\n" :: "n"(1));
        __syncthreads();

        unsigned bh[2][4];
#pragma unroll
        for (int j = 0; j < 2; j++)
            ldsm_x4(bh[j], uBh + boff + buf * STAGE_BYTES + j * 16 * PITCH * 2);

#pragma unroll
        for (int i = 0; i < 4; i++) {
            unsigned ah[4], al[4];
            ldsm_x4(ah, uAh + aoff + buf * STAGE_BYTES + i * 16 * PITCH * 2);
            ldsm_x4(al, uAl + aoff + buf * STAGE_BYTES + i * 16 * PITCH * 2);
#pragma unroll
            for (int j = 0; j < 4; j++) {
                unsigned b0 = bh[j >> 1][(j & 1)], b1 = bh[j >> 1][(j & 1) + 2];
                mma_bf16(acc[i][j], ah, b0, b1);
                mma_bf16(acc[i][j], al, b0, b1);
            }
        }

        const int pf = ks + 2;
        if (pf < NS) {
            cpa16(uAh + soff + pbuf * STAGE_BYTES, gah + (size_t)pf * 16);
            cpa16(uAl + soff + pbuf * STAGE_BYTES, gal + (size_t)pf * 16);
            cpa16(uBh + soff + pbuf * STAGE_BYTES, gbh + (size_t)pf * 16);
        }
        asm volatile("cp.async.commit_group;\n");
        buf = (buf == 2) ? 0 : buf + 1;
        pbuf = (pbuf == 2) ? 0 : pbuf + 1;
    }
    asm volatile("cp.async.wait_group 0;\n");

    const int lr = lane >> 2, lc = (lane & 3) * 2;
#pragma unroll
    for (int i = 0; i < 4; i++)
#pragma unroll
        for (int j = 0; j < 4; j++) {
            int r = m0 + wm * 64 + i * 16 + lr;
            int c = n0 + wn * 32 + j * 8 + lc;
            atomicAdd(&g_dotb[r * NATOMS + c],           acc[i][j][0]);
            atomicAdd(&g_dotb[r * NATOMS + c + 1],       acc[i][j][1]);
            atomicAdd(&g_dotb[(r + 8) * NATOMS + c],     acc[i][j][2]);
            atomicAdd(&g_dotb[(r + 8) * NATOMS + c + 1], acc[i][j][3]);
        }
}

// ---------------- K4b -------------------------------------------------------------
#define CLOSE_MARGIN 14.0f
__global__ void k4b_close() {
    int c = blockIdx.x, t = threadIdx.x;
    __shared__ float red[256];
    __shared__ int cnt, pos;
    if (t == 0) { cnt = 0; pos = 0; }
    float v = g_dotb[t * NATOMS + c];
    red[t] = v; __syncthreads();
    for (int s = 128; s > 0; s >>= 1) {
        if (t < s) red[t] = fmaxf(red[t], red[t + s]);
        __syncthreads();
    }
    float mx = red[0];
    bool cand = (v >= mx - CLOSE_MARGIN);
    if (cand) atomicAdd(&cnt, 1);
    __syncthreads();
    if (cnt >= 2) {
        if (t == 0) { int s = atomicAdd(&g_nccols, 1); g_ccol[s] = c; }
        if (cand) {
            int p = atomicAdd(&pos, 1);
            if (p < 8) { g_calist[c * 8 + p] = t; g_dotb[t * NATOMS + c] = 0.0f; }
        }
        __syncthreads();
        if (t == 0) g_cak[c] = (cnt < 8) ? cnt : 8;
    }
}

// ---------------- K5x --------------------------------------------------------------
__global__ __launch_bounds__(256) void k5x_exact(const float* __restrict__ x) {
    __shared__ float Msh[2 * 4096];
    __shared__ float red[256];
    int s = blockIdx.y;
    if (s >= g_nccols) return;
    int t = threadIdx.x;
    int c = g_ccol[s];
    int ka = g_cak[c];

    for (int i = t; i < 8192 / 4; i += 256)
        ((float4*)Msh)[i] = ((const float4*)g_M)[i];
    __syncthreads();

    int row = blockIdx.x * 256 + t;
    int p = (row / LDIM) & 1;
    const float* Mp = Msh + (p << 12);

    float xc[64];
    {
        const float4* xcp = (const float4*)(x + (size_t)c * GK + (size_t)row * 64);
#pragma unroll
        for (int i = 0; i < 16; i++) {
            float4 v = xcp[i];
            xc[4*i] = v.x; xc[4*i+1] = v.y; xc[4*i+2] = v.z; xc[4*i+3] = v.w;
        }
    }
    float z[64];
#pragma unroll 4
    for (int e = 0; e < 64; e++) {
        const float4* Mr = (const float4*)(Mp + e * 64);
        float sm = 0.0f;
#pragma unroll
        for (int f4 = 0; f4 < 16; f4++) {
            float4 m = Mr[f4];
            sm += m.x * xc[4*f4] + m.y * xc[4*f4+1] + m.z * xc[4*f4+2] + m.w * xc[4*f4+3];
        }
        z[e] = sm;
    }

    for (int j = 0; j < ka; j++) {
        int a = g_calist[c * 8 + j];
        const float4* xap = (const float4*)(x + (size_t)a * GK + (size_t)row * 64);
        float sd = 0.0f;
#pragma unroll
        for (int i = 0; i < 16; i++) {
            float4 v = xap[i];
            sd += v.x * z[4*i] + v.y * z[4*i+1] + v.z * z[4*i+2] + v.w * z[4*i+3];
        }
        red[t] = sd; __syncthreads();
        for (int st = 128; st > 0; st >>= 1) {
            if (t < st) red[t] += red[t + st];
            __syncthreads();
        }
        if (t == 0) atomicAdd(&g_dotb[a * NATOMS + c], red[0]);
        __syncthreads();
    }
}

// ---------------- K4: softmax -------------------------------------------------------
__global__ void k4_softmax() {
    int c = blockIdx.x, t = threadIdx.x;
    __shared__ float red[256];
    float v = g_dotb[t * NATOMS + c];
    red[t] = v; __syncthreads();
    for (int s = 128; s > 0; s >>= 1) {
        if (t < s) red[t] = fmaxf(red[t], red[t + s]);
        __syncthreads();
    }
    float mx = red[0]; __syncthreads();
    float e = expf(v - mx);
    red[t] = e; __syncthreads();
    for (int s = 128; s > 0; s >>= 1) {
        if (t < s) red[t] += red[t + s];
        __syncthreads();
    }
    g_w[t * NATOMS + c] = e / red[0];
}

// ---------------- K5: compact -------------------------------------------------------
__global__ void k5_compact() {
    int a = blockIdx.x, t = threadIdx.x;
    float wv = g_w[a * NATOMS + t];
    bool nz = (wv > 1e-7f);
    unsigned m = __ballot_sync(0xffffffffu, nz);
    int lane = t & 31, warp = t >> 5;
    int pre = __popc(m & ((1u << lane) - 1u));
    __shared__ int wcnt[8], woff[8];
    if (lane == 0) wcnt[warp] = __popc(m);
    __syncthreads();
    if (t == 0) {
        int s = 0;
        for (int i = 0; i < 8; i++) { woff[i] = s; s += wcnt[i]; }
        g_nnz[a] = s;
    }
    __syncthreads();
    if (nz) {
        int pos = woff[warp] + pre;
        g_idx[a * NATOMS + pos]  = t;
        g_wval[a * NATOMS + pos] = wv;
    }
}

// ---------------- K6V ----------------------------------------------------------------
__global__ __launch_bounds__(256, 4) void k6v(float* __restrict__ out) {
    __shared__ float wlist[NATOMS];
    __shared__ int   blist[NATOMS];
    __shared__ int   s_nnz;
    int t = threadIdx.x;
    int a = blockIdx.y;
    int r0 = blockIdx.x * 256;

    if (t == 0) s_nnz = g_nnz[a];
    __syncthreads();
    int nnz = s_nnz;

    int rowt = t >> 4;
    int e4   = (t & 15) * 4;

    if (nnz == 0) {
        float4 z = make_float4(0.f, 0.f, 0.f, 0.f);
#pragma unroll
        for (int i = 0; i < 16; i++) {
            int row = i * 16 + rowt;
            *(float4*)(out + (size_t)a * GK + (size_t)(r0 + row) * 64 + e4) = z;
        }
        return;
    }
    if (t < nnz) { blist[t] = g_idx[a * NATOMS + t]; wlist[t] = g_wval[a * NATOMS + t]; }
    __syncthreads();

#pragma unroll 2
    for (int i = 0; i < 16; i++) {
        int row = i * 16 + rowt;
        size_t off = (size_t)(r0 + row) * 64 + e4;
        float ax = 0.f, ay = 0.f, az = 0.f, aw = 0.f;
        int j = 0;
        for (; j + 1 < nnz; j += 2) {
            const float4 v0 = *(const float4*)(g_V + (size_t)blist[j]   * GK + off);
            const float4 v1 = *(const float4*)(g_V + (size_t)blist[j+1] * GK + off);
            float w0 = wlist[j], w1 = wlist[j+1];
            ax += w0*v0.x + w1*v1.x; ay += w0*v0.y + w1*v1.y;
            az += w0*v0.z + w1*v1.z; aw += w0*v0.w + w1*v1.w;
        }
        if (j < nnz) {
            const float4 v0 = *(const float4*)(g_V + (size_t)blist[j] * GK + off);
            float w0 = wlist[j];
            ax += w0*v0.x; ay += w0*v0.y; az += w0*v0.z; aw += w0*v0.w;
        }
        *(float4*)(out + (size_t)a * GK + off) = make_float4(ax, ay, az, aw);
    }
}

// ---------------- launch ---------------------------------------------------------------
extern "C" void kernel_launch(void* const* d_in, const int* in_sizes, int n_in,
                              void* d_out, int out_size) {
    const float* x  = (const float*)d_in[0];
    const float* Wq = (const float*)d_in[1];
    const float* Wk = (const float*)d_in[2];
    const float* Wv = (const float*)d_in[3];
    float* out = (float*)d_out;
    (void)in_sizes; (void)n_in; (void)out_size;

    const int k2v_smem = (4 * 64 * PB + 2 * 128 * PB) * 2;   // 73,728 B
    const int k3s_smem = 3 * 3 * STAGE_BYTES;                // 55,296 B
    cudaFuncSetAttribute(k2v,     cudaFuncAttributeMaxDynamicSharedMemorySize, k2v_smem);
    cudaFuncSetAttribute(k3s_dot, cudaFuncAttributeMaxDynamicSharedMemorySize, k3s_smem);

    k0_zero<<<(NATOMS * NATOMS + 255) / 256, 256>>>();
    k1_M<<<(PDIM * FDIM * FDIM + 255) / 256, 256>>>(Wq, Wk, Wv);
    {
        dim3 grid(HROWS / 128, 2);                 // 4608 x 2 parities
        k2v<<<grid, 256, k2v_smem>>>(x);
    }
    {
        dim3 grid(2, 2, GK / K3_KCHUNK);
        k3s_dot<<<grid, 256, k3s_smem>>>();
    }
    k4b_close<<<NATOMS, NATOMS>>>();
    {
        dim3 grid(18, NATOMS);
        k5x_exact<<<grid, 256>>>(x);
    }
    k4_softmax<<<NATOMS, NATOMS>>>();
    k5_compact<<<NATOMS, NATOMS>>>();
    {
        dim3 grid((NATOMS * PDIM * LDIM) / 256, NATOMS);
        k6v<<<grid, 256>>>(out);
    }
}

// round 8
// speedup vs baseline: 3.1085x; 1.2296x over previous
#include <cuda_runtime.h>
#include <cuda_bf16.h>
#include <cuda_fp16.h>

#define NATOMS 256
#define PDIM 2
#define LDIM 9
#define FDIM 64
#define ROWLEN (PDIM*LDIM*FDIM)                 // 1152
#define GK (NATOMS*ROWLEN)                      // 294912
#define NROWS_TOTAL (NATOMS*NATOMS*PDIM*LDIM)   // 1,179,648 rows of 64
#define HROWS (NROWS_TOTAL/2)

// ---------------- scratch ------------------------------------------------------
__device__ __half g_Th[NATOMS * GK];            // fp16 T
__device__ __half g_xh[NATOMS * GK];            // fp16 x
__device__ __half g_Vh[NATOMS * GK];            // fp16 V
__device__ float g_M[PDIM * FDIM * FDIM];
__device__ __nv_bfloat16 g_MtH[PDIM * FDIM * FDIM];
__device__ __nv_bfloat16 g_MtL[PDIM * FDIM * FDIM];
__device__ __nv_bfloat16 g_WvtH[PDIM * FDIM * FDIM];
__device__ __nv_bfloat16 g_WvtL[PDIM * FDIM * FDIM];
__device__ float g_dotb[NATOMS * NATOMS];
__device__ float g_w[NATOMS * NATOMS];
__device__ int   g_idx[NATOMS * NATOMS];
__device__ float g_wval[NATOMS * NATOMS];
__device__ int   g_nnz[NATOMS];
__device__ int   g_ccol[NATOMS];
__device__ int   g_calist[NATOMS * 8];
__device__ int   g_cak[NATOMS];
__device__ int   g_nccols;

extern __shared__ __nv_bfloat16 smdyn[];

// ---------------- K0 ------------------------------------------------------------
__global__ void k0_zero() {
    int i = blockIdx.x * blockDim.x + threadIdx.x;
    if (i < NATOMS * NATOMS) g_dotb[i] = 0.0f;
    if (i < NATOMS) g_nnz[i] = 0;
    if (i == 0) g_nccols = 0;
}

// ---------------- K1 ------------------------------------------------------------
__global__ void k1_M(const float* __restrict__ Wq, const float* __restrict__ Wk,
                     const float* __restrict__ Wv) {
    int id = blockIdx.x * blockDim.x + threadIdx.x;
    if (id >= PDIM * FDIM * FDIM) return;
    int p = id >> 12;
    int e = (id >> 6) & 63;
    int f = id & 63;
    const float* q = Wq + (p << 12) + (e << 6);
    const float* k = Wk + (p << 12) + (f << 6);
    float s = 0.0f;
#pragma unroll 16
    for (int g = 0; g < 64; g++) s += q[g] * k[g];
    g_M[id] = s;

    int tid = (p << 12) + (f << 6) + e;   // transposed [p][f][e]
    __nv_bfloat16 sh = __float2bfloat16_rn(s);
    g_MtH[tid] = sh;
    g_MtL[tid] = __float2bfloat16_rn(s - __bfloat162float(sh));

    float wv = Wv[id];
    __nv_bfloat16 wh = __float2bfloat16_rn(wv);
    g_WvtH[tid] = wh;
    g_WvtL[tid] = __float2bfloat16_rn(wv - __bfloat162float(wh));
}

// ---------------- helpers --------------------------------------------------------
static __device__ __forceinline__ void cpa16(unsigned sdst, const void* gsrc) {
    asm volatile("cp.async.cg.shared.global [%0], [%1], 16;\n" :: "r"(sdst), "l"(gsrc));
}
static __device__ __forceinline__ void ldsm_x4(unsigned r[4], unsigned addr) {
    asm volatile("ldmatrix.sync.aligned.m8n8.x4.shared.b16 {%0,%1,%2,%3}, [%4];\n"
        : "=r"(r[0]), "=r"(r[1]), "=r"(r[2]), "=r"(r[3]) : "r"(addr));
}
static __device__ __forceinline__ void mma_bf16(float d[4], const unsigned a[4],
                                                const unsigned b0, const unsigned b1) {
    asm volatile("mma.sync.aligned.m16n8k16.row.col.f32.bf16.bf16.f32 "
        "{%0,%1,%2,%3},{%4,%5,%6,%7},{%8,%9},{%0,%1,%2,%3};\n"
        : "+f"(d[0]), "+f"(d[1]), "+f"(d[2]), "+f"(d[3])
        : "r"(a[0]), "r"(a[1]), "r"(a[2]), "r"(a[3]), "r"(b0), "r"(b1));
}
static __device__ __forceinline__ void mma_f16(float d[4], const unsigned a[4],
                                               const unsigned b0, const unsigned b1) {
    asm volatile("mma.sync.aligned.m16n8k16.row.col.f32.f16.f16.f32 "
        "{%0,%1,%2,%3},{%4,%5,%6,%7},{%8,%9},{%0,%1,%2,%3};\n"
        : "+f"(d[0]), "+f"(d[1]), "+f"(d[2]), "+f"(d[3])
        : "r"(a[0]), "r"(a[1]), "r"(a[2]), "r"(a[3]), "r"(b0), "r"(b1));
}
static __device__ __forceinline__ unsigned pack_hi2(float a, float b) {
    __nv_bfloat162 h2 = __floats2bfloat162_rn(a, b);
    return *reinterpret_cast<unsigned*>(&h2);
}
static __device__ __forceinline__ unsigned pack_lo2(float a, float b) {
    float ra = a - __bfloat162float(__float2bfloat16_rn(a));
    float rb = b - __bfloat162float(__float2bfloat16_rn(b));
    __nv_bfloat162 h2 = __floats2bfloat162_rn(ra, rb);
    return *reinterpret_cast<unsigned*>(&h2);
}
static __device__ __forceinline__ unsigned pack_h2(float a, float b) {
    __half2 h2 = __floats2half2_rn(a, b);
    return *reinterpret_cast<unsigned*>(&h2);
}

// ---------------- K2V: parity-sorted tensor-core T/V, fp16 emissions ---------------
#define PB 72   // smem pitch (bf16): 144B rows -> conflict-free ldsm

__global__ __launch_bounds__(256, 2) void k2v(const float* __restrict__ x) {
    __nv_bfloat16* mtH = smdyn;
    __nv_bfloat16* mtL = mtH + 64 * PB;
    __nv_bfloat16* wvH = mtL + 64 * PB;
    __nv_bfloat16* wvL = wvH + 64 * PB;
    __nv_bfloat16* xtH = wvL + 64 * PB;
    __nv_bfloat16* xtL = xtH + 128 * PB;

    const int t = threadIdx.x;
    const int warp = t >> 5, lane = t & 31;
    const int P = blockIdx.y;
    const int r0 = blockIdx.x * 128;

    for (int i = t; i < 4096; i += 256) {
        int f = i >> 6, e = i & 63;
        int src = (P << 12) + i;
        mtH[f * PB + e] = g_MtH[src];
        mtL[f * PB + e] = g_MtL[src];
        wvH[f * PB + e] = g_WvtH[src];
        wvL[f * PB + e] = g_WvtL[src];
    }

    const int rloc = t >> 1;
    const int eh   = (t & 1) * 32;
    {
        int g = r0 + rloc;
        int q = g / 9, l = g - 9 * q;
        size_t gr = (size_t)(q * 18 + P * 9 + l);
        const float* gx = x + gr * 64 + eh;
        unsigned hxbuf[16];
#pragma unroll
        for (int qq = 0; qq < 8; qq++) {
            float4 v = *(const float4*)(gx + qq * 4);
            unsigned h01 = pack_hi2(v.x, v.y), h23 = pack_hi2(v.z, v.w);
            unsigned l01 = pack_lo2(v.x, v.y), l23 = pack_lo2(v.z, v.w);
            hxbuf[qq * 2]     = pack_h2(v.x, v.y);
            hxbuf[qq * 2 + 1] = pack_h2(v.z, v.w);
            *(unsigned*)(xtH + rloc * PB + eh + qq * 4)     = h01;
            *(unsigned*)(xtH + rloc * PB + eh + qq * 4 + 2) = h23;
            *(unsigned*)(xtL + rloc * PB + eh + qq * 4)     = l01;
            *(unsigned*)(xtL + rloc * PB + eh + qq * 4 + 2) = l23;
        }
        uint4* dh = (uint4*)(g_xh + gr * 64 + eh);
#pragma unroll
        for (int qq = 0; qq < 4; qq++)
            dh[qq] = make_uint4(hxbuf[4*qq], hxbuf[4*qq+1], hxbuf[4*qq+2], hxbuf[4*qq+3]);
    }
    __syncthreads();

    const unsigned uxh = (unsigned)__cvta_generic_to_shared(xtH);
    const unsigned uxl = (unsigned)__cvta_generic_to_shared(xtL);
    const unsigned umh = (unsigned)__cvta_generic_to_shared(mtH);
    const unsigned uml = (unsigned)__cvta_generic_to_shared(mtL);
    const unsigned uwh = (unsigned)__cvta_generic_to_shared(wvH);
    const unsigned uwl = (unsigned)__cvta_generic_to_shared(wvL);

    const int rowbase = warp * 16;
    const unsigned axoff = ((rowbase + (lane & 15)) * PB + (lane >> 4) * 8) * 2;
    const int lc = (lane & 3) * 2;

    const int raL = rowbase + (lane >> 2);
    size_t graA, graB;
    {
        int g = r0 + raL;      int q = g / 9, l = g - 9 * q;
        graA = (size_t)(q * 18 + P * 9 + l);
        g += 8;                q = g / 9; l = g - 9 * q;
        graB = (size_t)(q * 18 + P * 9 + l);
    }

    // ---- phase T (3-term bf16 split), fp16 out ----
    {
        float acc[8][4];
#pragma unroll
        for (int n = 0; n < 8; n++)
#pragma unroll
            for (int v = 0; v < 4; v++) acc[n][v] = 0.0f;

#pragma unroll
        for (int k = 0; k < 4; k++) {
            unsigned Ah[4], Al[4];
            ldsm_x4(Ah, uxh + axoff + k * 32);
            ldsm_x4(Al, uxl + axoff + k * 32);
#pragma unroll
            for (int n2 = 0; n2 < 4; n2++) {
                unsigned bo = ((n2 * 16 + (lane & 15)) * PB + (lane >> 4) * 8) * 2 + k * 32;
                unsigned Bh[4], Bl[4];
                ldsm_x4(Bh, umh + bo);
                mma_bf16(acc[2*n2],   Ah, Bh[0], Bh[2]);
                mma_bf16(acc[2*n2+1], Ah, Bh[1], Bh[3]);
                mma_bf16(acc[2*n2],   Al, Bh[0], Bh[2]);
                mma_bf16(acc[2*n2+1], Al, Bh[1], Bh[3]);
                ldsm_x4(Bl, uml + bo);
                mma_bf16(acc[2*n2],   Ah, Bl[0], Bl[2]);
                mma_bf16(acc[2*n2+1], Ah, Bl[1], Bl[3]);
            }
        }
        __half* thA = g_Th + graA * 64;
        __half* thB = g_Th + graB * 64;
#pragma unroll
        for (int n = 0; n < 8; n++) {
            int col = n * 8 + lc;
            *(unsigned*)(thA + col) = pack_h2(acc[n][0], acc[n][1]);
            *(unsigned*)(thB + col) = pack_h2(acc[n][2], acc[n][3]);
        }
    }

    // ---- phase V (3-term bf16 split), fp16 out ----
    {
        float acc[8][4];
#pragma unroll
        for (int n = 0; n < 8; n++)
#pragma unroll
            for (int v = 0; v < 4; v++) acc[n][v] = 0.0f;

#pragma unroll
        for (int k = 0; k < 4; k++) {
            unsigned Ah[4], Al[4];
            ldsm_x4(Ah, uxh + axoff + k * 32);
            ldsm_x4(Al, uxl + axoff + k * 32);
#pragma unroll
            for (int n2 = 0; n2 < 4; n2++) {
                unsigned bo = ((n2 * 16 + (lane & 15)) * PB + (lane >> 4) * 8) * 2 + k * 32;
                unsigned Bh[4], Bl[4];
                ldsm_x4(Bh, uwh + bo);
                mma_bf16(acc[2*n2],   Ah, Bh[0], Bh[2]);
                mma_bf16(acc[2*n2+1], Ah, Bh[1], Bh[3]);
                mma_bf16(acc[2*n2],   Al, Bh[0], Bh[2]);
                mma_bf16(acc[2*n2+1], Al, Bh[1], Bh[3]);
                ldsm_x4(Bl, uwl + bo);
                mma_bf16(acc[2*n2],   Ah, Bl[0], Bl[2]);
                mma_bf16(acc[2*n2+1], Ah, Bl[1], Bl[3]);
            }
        }
        __half* vA = g_Vh + graA * 64;
        __half* vB = g_Vh + graB * 64;
#pragma unroll
        for (int n = 0; n < 8; n++) {
            int col = n * 8 + lc;
            *(unsigned*)(vA + col) = pack_h2(acc[n][0], acc[n][1]);
            *(unsigned*)(vB + col) = pack_h2(acc[n][2], acc[n][3]);
        }
    }
}

// ---------------- K3s: dotb = Th * xh^T  (single fp16 term) -----------------------
#define K3_KCHUNK 4096
#define PITCH 24                         // 48B rows: conflict-free ldsm
#define STAGE_BYTES (128 * PITCH * 2)    // 6144
#define STAGE_ELEMS (128 * PITCH)

__global__ __launch_bounds__(256, 2) void k3s_dot() {
    __half* As = (__half*)smdyn;                 // [3][STAGE_ELEMS]
    __half* Bs = As + 3 * STAGE_ELEMS;

    const int t = threadIdx.x;
    const int m0 = blockIdx.x * 128, n0 = blockIdx.y * 128;
    const size_t kb = (size_t)blockIdx.z * K3_KCHUNK;

    const unsigned uA = (unsigned)__cvta_generic_to_shared(As);
    const unsigned uB = (unsigned)__cvta_generic_to_shared(Bs);

    const int row = t >> 1, half = t & 1;
    const size_t goff = (size_t)row * GK + kb + half * 8;
    const __half* ga = g_Th + (size_t)m0 * GK + goff;
    const __half* gb = g_xh + (size_t)n0 * GK + goff;
    const unsigned soff = (row * PITCH + half * 8) * 2;

    const int NS = K3_KCHUNK / 16;

#pragma unroll
    for (int s = 0; s < 2; s++) {
        cpa16(uA + soff + s * STAGE_BYTES, ga + (size_t)s * 16);
        cpa16(uB + soff + s * STAGE_BYTES, gb + (size_t)s * 16);
        asm volatile("cp.async.commit_group;\n");
    }

    const int warp = t >> 5, lane = t & 31;
    const int wm = warp >> 2, wn = warp & 3;
    const unsigned aoff = ((wm * 64 + (lane & 15)) * PITCH + (lane >> 4) * 8) * 2;
    const unsigned boff = ((wn * 32 + (lane & 15)) * PITCH + (lane >> 4) * 8) * 2;

    float acc[4][4][4] = {};

    int buf = 0, pbuf = 2;
    for (int ks = 0; ks < NS; ks++) {
        asm volatile("cp.async.wait_group %0;\n" :: "n"(1));
        __syncthreads();

        unsigned bh[2][4];
#pragma unroll
        for (int j = 0; j < 2; j++)
            ldsm_x4(bh[j], uB + boff + buf * STAGE_BYTES + j * 16 * PITCH * 2);

#pragma unroll
        for (int i = 0; i < 4; i++) {
            unsigned ah[4];
            ldsm_x4(ah, uA + aoff + buf * STAGE_BYTES + i * 16 * PITCH * 2);
#pragma unroll
            for (int j = 0; j < 4; j++) {
                unsigned b0 = bh[j >> 1][(j & 1)], b1 = bh[j >> 1][(j & 1) + 2];
                mma_f16(acc[i][j], ah, b0, b1);
            }
        }

        const int pf = ks + 2;
        if (pf < NS) {
            cpa16(uA + soff + pbuf * STAGE_BYTES, ga + (size_t)pf * 16);
            cpa16(uB + soff + pbuf * STAGE_BYTES, gb + (size_t)pf * 16);
        }
        asm volatile("cp.async.commit_group;\n");
        buf = (buf == 2) ? 0 : buf + 1;
        pbuf = (pbuf == 2) ? 0 : pbuf + 1;
    }
    asm volatile("cp.async.wait_group 0;\n");

    const int lr = lane >> 2, lc = (lane & 3) * 2;
#pragma unroll
    for (int i = 0; i < 4; i++)
#pragma unroll
        for (int j = 0; j < 4; j++) {
            int r = m0 + wm * 64 + i * 16 + lr;
            int c = n0 + wn * 32 + j * 8 + lc;
            atomicAdd(&g_dotb[r * NATOMS + c],           acc[i][j][0]);
            atomicAdd(&g_dotb[r * NATOMS + c + 1],       acc[i][j][1]);
            atomicAdd(&g_dotb[(r + 8) * NATOMS + c],     acc[i][j][2]);
            atomicAdd(&g_dotb[(r + 8) * NATOMS + c + 1], acc[i][j][3]);
        }
}

// ---------------- K4b -------------------------------------------------------------
#define CLOSE_MARGIN 14.0f
__global__ void k4b_close() {
    int c = blockIdx.x, t = threadIdx.x;
    __shared__ float red[256];
    __shared__ int cnt, pos;
    if (t == 0) { cnt = 0; pos = 0; }
    float v = g_dotb[t * NATOMS + c];
    red[t] = v; __syncthreads();
    for (int s = 128; s > 0; s >>= 1) {
        if (t < s) red[t] = fmaxf(red[t], red[t + s]);
        __syncthreads();
    }
    float mx = red[0];
    bool cand = (v >= mx - CLOSE_MARGIN);
    if (cand) atomicAdd(&cnt, 1);
    __syncthreads();
    if (cnt >= 2) {
        if (t == 0) { int s = atomicAdd(&g_nccols, 1); g_ccol[s] = c; }
        if (cand) {
            int p = atomicAdd(&pos, 1);
            if (p < 8) { g_calist[c * 8 + p] = t; g_dotb[t * NATOMS + c] = 0.0f; }
        }
        __syncthreads();
        if (t == 0) g_cak[c] = (cnt < 8) ? cnt : 8;
    }
}

// ---------------- K5x --------------------------------------------------------------
__global__ __launch_bounds__(256) void k5x_exact(const float* __restrict__ x) {
    __shared__ float Msh[2 * 4096];
    __shared__ float red[256];
    int s = blockIdx.y;
    if (s >= g_nccols) return;
    int t = threadIdx.x;
    int c = g_ccol[s];
    int ka = g_cak[c];

    for (int i = t; i < 8192 / 4; i += 256)
        ((float4*)Msh)[i] = ((const float4*)g_M)[i];
    __syncthreads();

    int row = blockIdx.x * 256 + t;
    int p = (row / LDIM) & 1;
    const float* Mp = Msh + (p << 12);

    float xc[64];
    {
        const float4* xcp = (const float4*)(x + (size_t)c * GK + (size_t)row * 64);
#pragma unroll
        for (int i = 0; i < 16; i++) {
            float4 v = xcp[i];
            xc[4*i] = v.x; xc[4*i+1] = v.y; xc[4*i+2] = v.z; xc[4*i+3] = v.w;
        }
    }
    float z[64];
#pragma unroll 4
    for (int e = 0; e < 64; e++) {
        const float4* Mr = (const float4*)(Mp + e * 64);
        float sm = 0.0f;
#pragma unroll
        for (int f4 = 0; f4 < 16; f4++) {
            float4 m = Mr[f4];
            sm += m.x * xc[4*f4] + m.y * xc[4*f4+1] + m.z * xc[4*f4+2] + m.w * xc[4*f4+3];
        }
        z[e] = sm;
    }

    for (int j = 0; j < ka; j++) {
        int a = g_calist[c * 8 + j];
        const float4* xap = (const float4*)(x + (size_t)a * GK + (size_t)row * 64);
        float sd = 0.0f;
#pragma unroll
        for (int i = 0; i < 16; i++) {
            float4 v = xap[i];
            sd += v.x * z[4*i] + v.y * z[4*i+1] + v.z * z[4*i+2] + v.w * z[4*i+3];
        }
        red[t] = sd; __syncthreads();
        for (int st = 128; st > 0; st >>= 1) {
            if (t < st) red[t] += red[t + st];
            __syncthreads();
        }
        if (t == 0) atomicAdd(&g_dotb[a * NATOMS + c], red[0]);
        __syncthreads();
    }
}

// ---------------- K4: softmax -------------------------------------------------------
__global__ void k4_softmax() {
    int c = blockIdx.x, t = threadIdx.x;
    __shared__ float red[256];
    float v = g_dotb[t * NATOMS + c];
    red[t] = v; __syncthreads();
    for (int s = 128; s > 0; s >>= 1) {
        if (t < s) red[t] = fmaxf(red[t], red[t + s]);
        __syncthreads();
    }
    float mx = red[0]; __syncthreads();
    float e = expf(v - mx);
    red[t] = e; __syncthreads();
    for (int s = 128; s > 0; s >>= 1) {
        if (t < s) red[t] += red[t + s];
        __syncthreads();
    }
    g_w[t * NATOMS + c] = e / red[0];
}

// ---------------- K5: compact -------------------------------------------------------
__global__ void k5_compact() {
    int a = blockIdx.x, t = threadIdx.x;
    float wv = g_w[a * NATOMS + t];
    bool nz = (wv > 1e-7f);
    unsigned m = __ballot_sync(0xffffffffu, nz);
    int lane = t & 31, warp = t >> 5;
    int pre = __popc(m & ((1u << lane) - 1u));
    __shared__ int wcnt[8], woff[8];
    if (lane == 0) wcnt[warp] = __popc(m);
    __syncthreads();
    if (t == 0) {
        int s = 0;
        for (int i = 0; i < 8; i++) { woff[i] = s; s += wcnt[i]; }
        g_nnz[a] = s;
    }
    __syncthreads();
    if (nz) {
        int pos = woff[warp] + pre;
        g_idx[a * NATOMS + pos]  = t;
        g_wval[a * NATOMS + pos] = wv;
    }
}

// ---------------- K6V: out[a] = sum_j w_j * Vh[b_j]  (fp16 gather-AXPY) -------------
__global__ __launch_bounds__(256, 4) void k6v(float* __restrict__ out) {
    __shared__ float wlist[NATOMS];
    __shared__ int   blist[NATOMS];
    __shared__ int   s_nnz;
    int t = threadIdx.x;
    int a = blockIdx.y;
    int r0 = blockIdx.x * 256;

    if (t == 0) s_nnz = g_nnz[a];
    __syncthreads();
    int nnz = s_nnz;

    int rowt = t >> 4;
    int e4   = (t & 15) * 4;

    if (nnz == 0) {
        float4 z = make_float4(0.f, 0.f, 0.f, 0.f);
#pragma unroll
        for (int i = 0; i < 16; i++) {
            int row = i * 16 + rowt;
            *(float4*)(out + (size_t)a * GK + (size_t)(r0 + row) * 64 + e4) = z;
        }
        return;
    }
    if (t < nnz) { blist[t] = g_idx[a * NATOMS + t]; wlist[t] = g_wval[a * NATOMS + t]; }
    __syncthreads();

#pragma unroll 2
    for (int i = 0; i < 16; i++) {
        int row = i * 16 + rowt;
        size_t off = (size_t)(r0 + row) * 64 + e4;
        float ax = 0.f, ay = 0.f, az = 0.f, aw = 0.f;
        int j = 0;
        for (; j + 1 < nnz; j += 2) {
            uint2 u0 = *(const uint2*)(g_Vh + (size_t)blist[j]   * GK + off);
            uint2 u1 = *(const uint2*)(g_Vh + (size_t)blist[j+1] * GK + off);
            float2 f00 = __half22float2(*(__half2*)&u0.x);
            float2 f01 = __half22float2(*(__half2*)&u0.y);
            float2 f10 = __half22float2(*(__half2*)&u1.x);
            float2 f11 = __half22float2(*(__half2*)&u1.y);
            float w0 = wlist[j], w1 = wlist[j+1];
            ax += w0*f00.x + w1*f10.x; ay += w0*f00.y + w1*f10.y;
            az += w0*f01.x + w1*f11.x; aw += w0*f01.y + w1*f11.y;
        }
        if (j < nnz) {
            uint2 u0 = *(const uint2*)(g_Vh + (size_t)blist[j] * GK + off);
            float2 f00 = __half22float2(*(__half2*)&u0.x);
            float2 f01 = __half22float2(*(__half2*)&u0.y);
            float w0 = wlist[j];
            ax += w0*f00.x; ay += w0*f00.y; az += w0*f01.x; aw += w0*f01.y;
        }
        *(float4*)(out + (size_t)a * GK + off) = make_float4(ax, ay, az, aw);
    }
}

// ---------------- launch ---------------------------------------------------------------
extern "C" void kernel_launch(void* const* d_in, const int* in_sizes, int n_in,
                              void* d_out, int out_size) {
    const float* x  = (const float*)d_in[0];
    const float* Wq = (const float*)d_in[1];
    const float* Wk = (const float*)d_in[2];
    const float* Wv = (const float*)d_in[3];
    float* out = (float*)d_out;
    (void)in_sizes; (void)n_in; (void)out_size;

    const int k2v_smem = (4 * 64 * PB + 2 * 128 * PB) * 2;   // 73,728 B
    const int k3s_smem = 2 * 3 * STAGE_BYTES;                // 36,864 B
    cudaFuncSetAttribute(k2v,     cudaFuncAttributeMaxDynamicSharedMemorySize, k2v_smem);
    cudaFuncSetAttribute(k3s_dot, cudaFuncAttributeMaxDynamicSharedMemorySize, k3s_smem);

    k0_zero<<<(NATOMS * NATOMS + 255) / 256, 256>>>();
    k1_M<<<(PDIM * FDIM * FDIM + 255) / 256, 256>>>(Wq, Wk, Wv);
    {
        dim3 grid(HROWS / 128, 2);
        k2v<<<grid, 256, k2v_smem>>>(x);
    }
    {
        dim3 grid(2, 2, GK / K3_KCHUNK);
        k3s_dot<<<grid, 256, k3s_smem>>>();
    }
    k4b_close<<<NATOMS, NATOMS>>>();
    {
        dim3 grid(18, NATOMS);
        k5x_exact<<<grid, 256>>>(x);
    }
    k4_softmax<<<NATOMS, NATOMS>>>();
    k5_compact<<<NATOMS, NATOMS>>>();
    {
        dim3 grid((NATOMS * PDIM * LDIM) / 256, NATOMS);
        k6v<<<grid, 256>>>(out);
    }
}

// round 9
// speedup vs baseline: 3.2067x; 1.0316x over previous
#include <cuda_runtime.h>
#include <cuda_bf16.h>
#include <cuda_fp16.h>

#define NATOMS 256
#define PDIM 2
#define LDIM 9
#define FDIM 64
#define ROWLEN (PDIM*LDIM*FDIM)                 // 1152
#define GK (NATOMS*ROWLEN)                      // 294912
#define NROWS_TOTAL (NATOMS*NATOMS*PDIM*LDIM)   // 1,179,648 rows of 64
#define HROWS (NROWS_TOTAL/2)

// ---------------- scratch ------------------------------------------------------
__device__ __half g_Th[NATOMS * GK];            // fp16 T
__device__ __half g_xh[NATOMS * GK];            // fp16 x
__device__ __half g_Vh[NATOMS * GK];            // fp16 V
__device__ float g_M[PDIM * FDIM * FDIM];
__device__ __nv_bfloat16 g_MtH[PDIM * FDIM * FDIM];
__device__ __nv_bfloat16 g_WvtH[PDIM * FDIM * FDIM];
__device__ __nv_bfloat16 g_WvtL[PDIM * FDIM * FDIM];
__device__ float g_dotb[NATOMS * NATOMS];
__device__ float g_w[NATOMS * NATOMS];
__device__ int   g_idx[NATOMS * NATOMS];
__device__ float g_wval[NATOMS * NATOMS];
__device__ int   g_nnz[NATOMS];
__device__ int   g_ccol[NATOMS];
__device__ int   g_calist[NATOMS * 8];
__device__ int   g_cak[NATOMS];
__device__ int   g_nccols;

extern __shared__ __nv_bfloat16 smdyn[];

// ---------------- K0 ------------------------------------------------------------
__global__ void k0_zero() {
    int i = blockIdx.x * blockDim.x + threadIdx.x;
    if (i < NATOMS * NATOMS) g_dotb[i] = 0.0f;
    if (i < NATOMS) g_nnz[i] = 0;
    if (i == 0) g_nccols = 0;
}

// ---------------- K1 ------------------------------------------------------------
__global__ void k1_M(const float* __restrict__ Wq, const float* __restrict__ Wk,
                     const float* __restrict__ Wv) {
    int id = blockIdx.x * blockDim.x + threadIdx.x;
    if (id >= PDIM * FDIM * FDIM) return;
    int p = id >> 12;
    int e = (id >> 6) & 63;
    int f = id & 63;
    const float* q = Wq + (p << 12) + (e << 6);
    const float* k = Wk + (p << 12) + (f << 6);
    float s = 0.0f;
#pragma unroll 16
    for (int g = 0; g < 64; g++) s += q[g] * k[g];
    g_M[id] = s;

    int tid = (p << 12) + (f << 6) + e;   // transposed [p][f][e]
    g_MtH[tid] = __float2bfloat16_rn(s);

    float wv = Wv[id];
    __nv_bfloat16 wh = __float2bfloat16_rn(wv);
    g_WvtH[tid] = wh;
    g_WvtL[tid] = __float2bfloat16_rn(wv - __bfloat162float(wh));
}

// ---------------- helpers --------------------------------------------------------
static __device__ __forceinline__ void cpa16(unsigned sdst, const void* gsrc) {
    asm volatile("cp.async.cg.shared.global [%0], [%1], 16;\n" :: "r"(sdst), "l"(gsrc));
}
static __device__ __forceinline__ void ldsm_x4(unsigned r[4], unsigned addr) {
    asm volatile("ldmatrix.sync.aligned.m8n8.x4.shared.b16 {%0,%1,%2,%3}, [%4];\n"
        : "=r"(r[0]), "=r"(r[1]), "=r"(r[2]), "=r"(r[3]) : "r"(addr));
}
static __device__ __forceinline__ void mma_bf16(float d[4], const unsigned a[4],
                                                const unsigned b0, const unsigned b1) {
    asm volatile("mma.sync.aligned.m16n8k16.row.col.f32.bf16.bf16.f32 "
        "{%0,%1,%2,%3},{%4,%5,%6,%7},{%8,%9},{%0,%1,%2,%3};\n"
        : "+f"(d[0]), "+f"(d[1]), "+f"(d[2]), "+f"(d[3])
        : "r"(a[0]), "r"(a[1]), "r"(a[2]), "r"(a[3]), "r"(b0), "r"(b1));
}
static __device__ __forceinline__ void mma_f16(float d[4], const unsigned a[4],
                                               const unsigned b0, const unsigned b1) {
    asm volatile("mma.sync.aligned.m16n8k16.row.col.f32.f16.f16.f32 "
        "{%0,%1,%2,%3},{%4,%5,%6,%7},{%8,%9},{%0,%1,%2,%3};\n"
        : "+f"(d[0]), "+f"(d[1]), "+f"(d[2]), "+f"(d[3])
        : "r"(a[0]), "r"(a[1]), "r"(a[2]), "r"(a[3]), "r"(b0), "r"(b1));
}
static __device__ __forceinline__ unsigned pack_hi2(float a, float b) {
    __nv_bfloat162 h2 = __floats2bfloat162_rn(a, b);
    return *reinterpret_cast<unsigned*>(&h2);
}
static __device__ __forceinline__ unsigned pack_lo2(float a, float b) {
    float ra = a - __bfloat162float(__float2bfloat16_rn(a));
    float rb = b - __bfloat162float(__float2bfloat16_rn(b));
    __nv_bfloat162 h2 = __floats2bfloat162_rn(ra, rb);
    return *reinterpret_cast<unsigned*>(&h2);
}
static __device__ __forceinline__ unsigned pack_h2(float a, float b) {
    __half2 h2 = __floats2half2_rn(a, b);
    return *reinterpret_cast<unsigned*>(&h2);
}

// ---------------- K2V: parity-sorted tensor-core T/V, coalesced fp16 emits ---------
#define PB 72   // smem pitch (bf16/fp16 elems): 144B rows -> conflict-free ldsm

__global__ __launch_bounds__(256, 2) void k2v(const float* __restrict__ x) {
    __nv_bfloat16* mtH = smdyn;                 // [64][PB]
    __nv_bfloat16* wvH = mtH + 64 * PB;         // [64][PB]
    __nv_bfloat16* wvL = wvH + 64 * PB;         // [64][PB]
    __nv_bfloat16* xtH = wvL + 64 * PB;         // [128][PB]
    __nv_bfloat16* xtL = xtH + 128 * PB;        // [128][PB]
    __half*        stg = (__half*)(xtL + 128 * PB);   // [128][PB] output staging

    const int t = threadIdx.x;
    const int warp = t >> 5, lane = t & 31;
    const int P = blockIdx.y;
    const int r0 = blockIdx.x * 128;

    for (int i = t; i < 4096; i += 256) {
        int f = i >> 6, e = i & 63;
        int src = (P << 12) + i;
        mtH[f * PB + e] = g_MtH[src];
        wvH[f * PB + e] = g_WvtH[src];
        wvL[f * PB + e] = g_WvtL[src];
    }

    const int rloc = t >> 1;
    const int eh   = (t & 1) * 32;
    size_t grW;     // writer thread's global row
    {
        int g = r0 + rloc;
        int q = g / 9, l = g - 9 * q;
        grW = (size_t)(q * 18 + P * 9 + l);
        const float* gx = x + grW * 64 + eh;
        unsigned hxbuf[16];
#pragma unroll
        for (int qq = 0; qq < 8; qq++) {
            float4 v = *(const float4*)(gx + qq * 4);
            unsigned h01 = pack_hi2(v.x, v.y), h23 = pack_hi2(v.z, v.w);
            unsigned l01 = pack_lo2(v.x, v.y), l23 = pack_lo2(v.z, v.w);
            hxbuf[qq * 2]     = pack_h2(v.x, v.y);
            hxbuf[qq * 2 + 1] = pack_h2(v.z, v.w);
            *(unsigned*)(xtH + rloc * PB + eh + qq * 4)     = h01;
            *(unsigned*)(xtH + rloc * PB + eh + qq * 4 + 2) = h23;
            *(unsigned*)(xtL + rloc * PB + eh + qq * 4)     = l01;
            *(unsigned*)(xtL + rloc * PB + eh + qq * 4 + 2) = l23;
        }
        uint4* dh = (uint4*)(g_xh + grW * 64 + eh);
#pragma unroll
        for (int qq = 0; qq < 4; qq++)
            dh[qq] = make_uint4(hxbuf[4*qq], hxbuf[4*qq+1], hxbuf[4*qq+2], hxbuf[4*qq+3]);
    }
    __syncthreads();

    const unsigned uxh = (unsigned)__cvta_generic_to_shared(xtH);
    const unsigned uxl = (unsigned)__cvta_generic_to_shared(xtL);
    const unsigned umh = (unsigned)__cvta_generic_to_shared(mtH);
    const unsigned uwh = (unsigned)__cvta_generic_to_shared(wvH);
    const unsigned uwl = (unsigned)__cvta_generic_to_shared(wvL);

    const int rowbase = warp * 16;
    const unsigned axoff = ((rowbase + (lane & 15)) * PB + (lane >> 4) * 8) * 2;
    const int lc = (lane & 3) * 2;
    const int raL = rowbase + (lane >> 2);      // local fragment row (and raL+8)

    // ---- phase T: 2-term bf16 split (xh+xl)·Mh, staged fp16 out ----
    {
        float acc[8][4];
#pragma unroll
        for (int n = 0; n < 8; n++)
#pragma unroll
            for (int v = 0; v < 4; v++) acc[n][v] = 0.0f;

#pragma unroll
        for (int k = 0; k < 4; k++) {
            unsigned Ah[4], Al[4];
            ldsm_x4(Ah, uxh + axoff + k * 32);
            ldsm_x4(Al, uxl + axoff + k * 32);
#pragma unroll
            for (int n2 = 0; n2 < 4; n2++) {
                unsigned bo = ((n2 * 16 + (lane & 15)) * PB + (lane >> 4) * 8) * 2 + k * 32;
                unsigned Bh[4];
                ldsm_x4(Bh, umh + bo);
                mma_bf16(acc[2*n2],   Ah, Bh[0], Bh[2]);
                mma_bf16(acc[2*n2+1], Ah, Bh[1], Bh[3]);
                mma_bf16(acc[2*n2],   Al, Bh[0], Bh[2]);
                mma_bf16(acc[2*n2+1], Al, Bh[1], Bh[3]);
            }
        }
#pragma unroll
        for (int n = 0; n < 8; n++) {
            int col = n * 8 + lc;
            *(unsigned*)(stg + raL * PB + col)       = pack_h2(acc[n][0], acc[n][1]);
            *(unsigned*)(stg + (raL + 8) * PB + col) = pack_h2(acc[n][2], acc[n][3]);
        }
        __syncthreads();
        // coalesced writer: 2 threads/row, 64B each
        const uint4* s4 = (const uint4*)(stg + rloc * PB + eh);
        uint4* d4 = (uint4*)(g_Th + grW * 64 + eh);
#pragma unroll
        for (int qq = 0; qq < 4; qq++) d4[qq] = s4[qq];
        __syncthreads();
    }

    // ---- phase V: 3-term bf16 split, staged fp16 out ----
    {
        float acc[8][4];
#pragma unroll
        for (int n = 0; n < 8; n++)
#pragma unroll
            for (int v = 0; v < 4; v++) acc[n][v] = 0.0f;

#pragma unroll
        for (int k = 0; k < 4; k++) {
            unsigned Ah[4], Al[4];
            ldsm_x4(Ah, uxh + axoff + k * 32);
            ldsm_x4(Al, uxl + axoff + k * 32);
#pragma unroll
            for (int n2 = 0; n2 < 4; n2++) {
                unsigned bo = ((n2 * 16 + (lane & 15)) * PB + (lane >> 4) * 8) * 2 + k * 32;
                unsigned Bh[4], Bl[4];
                ldsm_x4(Bh, uwh + bo);
                mma_bf16(acc[2*n2],   Ah, Bh[0], Bh[2]);
                mma_bf16(acc[2*n2+1], Ah, Bh[1], Bh[3]);
                mma_bf16(acc[2*n2],   Al, Bh[0], Bh[2]);
                mma_bf16(acc[2*n2+1], Al, Bh[1], Bh[3]);
                ldsm_x4(Bl, uwl + bo);
                mma_bf16(acc[2*n2],   Ah, Bl[0], Bl[2]);
                mma_bf16(acc[2*n2+1], Ah, Bl[1], Bl[3]);
            }
        }
#pragma unroll
        for (int n = 0; n < 8; n++) {
            int col = n * 8 + lc;
            *(unsigned*)(stg + raL * PB + col)       = pack_h2(acc[n][0], acc[n][1]);
            *(unsigned*)(stg + (raL + 8) * PB + col) = pack_h2(acc[n][2], acc[n][3]);
        }
        __syncthreads();
        const uint4* s4 = (const uint4*)(stg + rloc * PB + eh);
        uint4* d4 = (uint4*)(g_Vh + grW * 64 + eh);
#pragma unroll
        for (int qq = 0; qq < 4; qq++) d4[qq] = s4[qq];
    }
}

// ---------------- K3s: dotb = Th * xh^T (fp16, 6-stage pipeline) ------------------
#define K3_KCHUNK 4096
#define K3_STAGES 6
#define PITCH 24                         // 48B rows: conflict-free ldsm
#define STAGE_BYTES (128 * PITCH * 2)    // 6144
#define STAGE_ELEMS (128 * PITCH)

__global__ __launch_bounds__(256, 2) void k3s_dot() {
    __half* As = (__half*)smdyn;                 // [6][STAGE_ELEMS]
    __half* Bs = As + K3_STAGES * STAGE_ELEMS;

    const int t = threadIdx.x;
    const int m0 = blockIdx.x * 128, n0 = blockIdx.y * 128;
    const size_t kb = (size_t)blockIdx.z * K3_KCHUNK;

    const unsigned uA = (unsigned)__cvta_generic_to_shared(As);
    const unsigned uB = (unsigned)__cvta_generic_to_shared(Bs);

    const int row = t >> 1, half = t & 1;
    const size_t goff = (size_t)row * GK + kb + half * 8;
    const __half* ga = g_Th + (size_t)m0 * GK + goff;
    const __half* gb = g_xh + (size_t)n0 * GK + goff;
    const unsigned soff = (row * PITCH + half * 8) * 2;

    const int NS = K3_KCHUNK / 16;

#pragma unroll
    for (int s = 0; s < K3_STAGES - 1; s++) {
        cpa16(uA + soff + s * STAGE_BYTES, ga + (size_t)s * 16);
        cpa16(uB + soff + s * STAGE_BYTES, gb + (size_t)s * 16);
        asm volatile("cp.async.commit_group;\n");
    }

    const int warp = t >> 5, lane = t & 31;
    const int wm = warp >> 2, wn = warp & 3;
    const unsigned aoff = ((wm * 64 + (lane & 15)) * PITCH + (lane >> 4) * 8) * 2;
    const unsigned boff = ((wn * 32 + (lane & 15)) * PITCH + (lane >> 4) * 8) * 2;

    float acc[4][4][4] = {};

    int buf = 0, pbuf = K3_STAGES - 1;
    for (int ks = 0; ks < NS; ks++) {
        asm volatile("cp.async.wait_group %0;\n" :: "n"(K3_STAGES - 2));
        __syncthreads();

        unsigned bh[2][4];
#pragma unroll
        for (int j = 0; j < 2; j++)
            ldsm_x4(bh[j], uB + boff + buf * STAGE_BYTES + j * 16 * PITCH * 2);

#pragma unroll
        for (int i = 0; i < 4; i++) {
            unsigned ah[4];
            ldsm_x4(ah, uA + aoff + buf * STAGE_BYTES + i * 16 * PITCH * 2);
#pragma unroll
            for (int j = 0; j < 4; j++) {
                unsigned b0 = bh[j >> 1][(j & 1)], b1 = bh[j >> 1][(j & 1) + 2];
                mma_f16(acc[i][j], ah, b0, b1);
            }
        }

        const int pf = ks + K3_STAGES - 1;
        if (pf < NS) {
            cpa16(uA + soff + pbuf * STAGE_BYTES, ga + (size_t)pf * 16);
            cpa16(uB + soff + pbuf * STAGE_BYTES, gb + (size_t)pf * 16);
        }
        asm volatile("cp.async.commit_group;\n");
        buf  = (buf  == K3_STAGES - 1) ? 0 : buf  + 1;
        pbuf = (pbuf == K3_STAGES - 1) ? 0 : pbuf + 1;
    }
    asm volatile("cp.async.wait_group 0;\n");

    const int lr = lane >> 2, lc = (lane & 3) * 2;
#pragma unroll
    for (int i = 0; i < 4; i++)
#pragma unroll
        for (int j = 0; j < 4; j++) {
            int r = m0 + wm * 64 + i * 16 + lr;
            int c = n0 + wn * 32 + j * 8 + lc;
            atomicAdd(&g_dotb[r * NATOMS + c],           acc[i][j][0]);
            atomicAdd(&g_dotb[r * NATOMS + c + 1],       acc[i][j][1]);
            atomicAdd(&g_dotb[(r + 8) * NATOMS + c],     acc[i][j][2]);
            atomicAdd(&g_dotb[(r + 8) * NATOMS + c + 1], acc[i][j][3]);
        }
}

// ---------------- K4b -------------------------------------------------------------
#define CLOSE_MARGIN 14.0f
__global__ void k4b_close() {
    int c = blockIdx.x, t = threadIdx.x;
    __shared__ float red[256];
    __shared__ int cnt, pos;
    if (t == 0) { cnt = 0; pos = 0; }
    float v = g_dotb[t * NATOMS + c];
    red[t] = v; __syncthreads();
    for (int s = 128; s > 0; s >>= 1) {
        if (t < s) red[t] = fmaxf(red[t], red[t + s]);
        __syncthreads();
    }
    float mx = red[0];
    bool cand = (v >= mx - CLOSE_MARGIN);
    if (cand) atomicAdd(&cnt, 1);
    __syncthreads();
    if (cnt >= 2) {
        if (t == 0) { int s = atomicAdd(&g_nccols, 1); g_ccol[s] = c; }
        if (cand) {
            int p = atomicAdd(&pos, 1);
            if (p < 8) { g_calist[c * 8 + p] = t; g_dotb[t * NATOMS + c] = 0.0f; }
        }
        __syncthreads();
        if (t == 0) g_cak[c] = (cnt < 8) ? cnt : 8;
    }
}

// ---------------- K5x --------------------------------------------------------------
__global__ __launch_bounds__(256) void k5x_exact(const float* __restrict__ x) {
    __shared__ float Msh[2 * 4096];
    __shared__ float red[256];
    int s = blockIdx.y;
    if (s >= g_nccols) return;
    int t = threadIdx.x;
    int c = g_ccol[s];
    int ka = g_cak[c];

    for (int i = t; i < 8192 / 4; i += 256)
        ((float4*)Msh)[i] = ((const float4*)g_M)[i];
    __syncthreads();

    int row = blockIdx.x * 256 + t;
    int p = (row / LDIM) & 1;
    const float* Mp = Msh + (p << 12);

    float xc[64];
    {
        const float4* xcp = (const float4*)(x + (size_t)c * GK + (size_t)row * 64);
#pragma unroll
        for (int i = 0; i < 16; i++) {
            float4 v = xcp[i];
            xc[4*i] = v.x; xc[4*i+1] = v.y; xc[4*i+2] = v.z; xc[4*i+3] = v.w;
        }
    }
    float z[64];
#pragma unroll 4
    for (int e = 0; e < 64; e++) {
        const float4* Mr = (const float4*)(Mp + e * 64);
        float sm = 0.0f;
#pragma unroll
        for (int f4 = 0; f4 < 16; f4++) {
            float4 m = Mr[f4];
            sm += m.x * xc[4*f4] + m.y * xc[4*f4+1] + m.z * xc[4*f4+2] + m.w * xc[4*f4+3];
        }
        z[e] = sm;
    }

    for (int j = 0; j < ka; j++) {
        int a = g_calist[c * 8 + j];
        const float4* xap = (const float4*)(x + (size_t)a * GK + (size_t)row * 64);
        float sd = 0.0f;
#pragma unroll
        for (int i = 0; i < 16; i++) {
            float4 v = xap[i];
            sd += v.x * z[4*i] + v.y * z[4*i+1] + v.z * z[4*i+2] + v.w * z[4*i+3];
        }
        red[t] = sd; __syncthreads();
        for (int st = 128; st > 0; st >>= 1) {
            if (t < st) red[t] += red[t + st];
            __syncthreads();
        }
        if (t == 0) atomicAdd(&g_dotb[a * NATOMS + c], red[0]);
        __syncthreads();
    }
}

// ---------------- K4: softmax -------------------------------------------------------
__global__ void k4_softmax() {
    int c = blockIdx.x, t = threadIdx.x;
    __shared__ float red[256];
    float v = g_dotb[t * NATOMS + c];
    red[t] = v; __syncthreads();
    for (int s = 128; s > 0; s >>= 1) {
        if (t < s) red[t] = fmaxf(red[t], red[t + s]);
        __syncthreads();
    }
    float mx = red[0]; __syncthreads();
    float e = expf(v - mx);
    red[t] = e; __syncthreads();
    for (int s = 128; s > 0; s >>= 1) {
        if (t < s) red[t] += red[t + s];
        __syncthreads();
    }
    g_w[t * NATOMS + c] = e / red[0];
}

// ---------------- K5: compact -------------------------------------------------------
__global__ void k5_compact() {
    int a = blockIdx.x, t = threadIdx.x;
    float wv = g_w[a * NATOMS + t];
    bool nz = (wv > 1e-7f);
    unsigned m = __ballot_sync(0xffffffffu, nz);
    int lane = t & 31, warp = t >> 5;
    int pre = __popc(m & ((1u << lane) - 1u));
    __shared__ int wcnt[8], woff[8];
    if (lane == 0) wcnt[warp] = __popc(m);
    __syncthreads();
    if (t == 0) {
        int s = 0;
        for (int i = 0; i < 8; i++) { woff[i] = s; s += wcnt[i]; }
        g_nnz[a] = s;
    }
    __syncthreads();
    if (nz) {
        int pos = woff[warp] + pre;
        g_idx[a * NATOMS + pos]  = t;
        g_wval[a * NATOMS + pos] = wv;
    }
}

// ---------------- K6V: out[a] = sum_j w_j * Vh[b_j]  (fp16 gather-AXPY) -------------
__global__ __launch_bounds__(256, 4) void k6v(float* __restrict__ out) {
    __shared__ float wlist[NATOMS];
    __shared__ int   blist[NATOMS];
    __shared__ int   s_nnz;
    int t = threadIdx.x;
    int a = blockIdx.y;
    int r0 = blockIdx.x * 256;

    if (t == 0) s_nnz = g_nnz[a];
    __syncthreads();
    int nnz = s_nnz;

    int rowt = t >> 4;
    int e4   = (t & 15) * 4;

    if (nnz == 0) {
        float4 z = make_float4(0.f, 0.f, 0.f, 0.f);
#pragma unroll
        for (int i = 0; i < 16; i++) {
            int row = i * 16 + rowt;
            *(float4*)(out + (size_t)a * GK + (size_t)(r0 + row) * 64 + e4) = z;
        }
        return;
    }
    if (t < nnz) { blist[t] = g_idx[a * NATOMS + t]; wlist[t] = g_wval[a * NATOMS + t]; }
    __syncthreads();

#pragma unroll 2
    for (int i = 0; i < 16; i++) {
        int row = i * 16 + rowt;
        size_t off = (size_t)(r0 + row) * 64 + e4;
        float ax = 0.f, ay = 0.f, az = 0.f, aw = 0.f;
        int j = 0;
        for (; j + 1 < nnz; j += 2) {
            uint2 u0 = *(const uint2*)(g_Vh + (size_t)blist[j]   * GK + off);
            uint2 u1 = *(const uint2*)(g_Vh + (size_t)blist[j+1] * GK + off);
            float2 f00 = __half22float2(*(__half2*)&u0.x);
            float2 f01 = __half22float2(*(__half2*)&u0.y);
            float2 f10 = __half22float2(*(__half2*)&u1.x);
            float2 f11 = __half22float2(*(__half2*)&u1.y);
            float w0 = wlist[j], w1 = wlist[j+1];
            ax += w0*f00.x + w1*f10.x; ay += w0*f00.y + w1*f10.y;
            az += w0*f01.x + w1*f11.x; aw += w0*f01.y + w1*f11.y;
        }
        if (j < nnz) {
            uint2 u0 = *(const uint2*)(g_Vh + (size_t)blist[j] * GK + off);
            float2 f00 = __half22float2(*(__half2*)&u0.x);
            float2 f01 = __half22float2(*(__half2*)&u0.y);
            float w0 = wlist[j];
            ax += w0*f00.x; ay += w0*f00.y; az += w0*f01.x; aw += w0*f01.y;
        }
        *(float4*)(out + (size_t)a * GK + off) = make_float4(ax, ay, az, aw);
    }
}

// ---------------- launch ---------------------------------------------------------------
extern "C" void kernel_launch(void* const* d_in, const int* in_sizes, int n_in,
                              void* d_out, int out_size) {
    const float* x  = (const float*)d_in[0];
    const float* Wq = (const float*)d_in[1];
    const float* Wk = (const float*)d_in[2];
    const float* Wv = (const float*)d_in[3];
    float* out = (float*)d_out;
    (void)in_sizes; (void)n_in; (void)out_size;

    const int k2v_smem = (3 * 64 * PB + 3 * 128 * PB) * 2;      // 82,944 B
    const int k3s_smem = 2 * K3_STAGES * STAGE_BYTES;           // 73,728 B
    cudaFuncSetAttribute(k2v,     cudaFuncAttributeMaxDynamicSharedMemorySize, k2v_smem);
    cudaFuncSetAttribute(k3s_dot, cudaFuncAttributeMaxDynamicSharedMemorySize, k3s_smem);

    k0_zero<<<(NATOMS * NATOMS + 255) / 256, 256>>>();
    k1_M<<<(PDIM * FDIM * FDIM + 255) / 256, 256>>>(Wq, Wk, Wv);
    {
        dim3 grid(HROWS / 128, 2);
        k2v<<<grid, 256, k2v_smem>>>(x);
    }
    {
        dim3 grid(2, 2, GK / K3_KCHUNK);
        k3s_dot<<<grid, 256, k3s_smem>>>();
    }
    k4b_close<<<NATOMS, NATOMS>>>();
    {
        dim3 grid(18, NATOMS);
        k5x_exact<<<grid, 256>>>(x);
    }
    k4_softmax<<<NATOMS, NATOMS>>>();
    k5_compact<<<NATOMS, NATOMS>>>();
    {
        dim3 grid((NATOMS * PDIM * LDIM) / 256, NATOMS);
        k6v<<<grid, 256>>>(out);
    }
}